// round 1
// baseline (speedup 1.0000x reference)
#include <cuda_runtime.h>
#include <cuda_bf16.h>

// ---------------------------------------------------------------------------
// Mamba block, fp32 baseline.
// Shapes: BATCH=2, SEQ=1024, D_MODEL=1024, D_INNER=2048, DT_RANK=64,
//         D_STATE=16, D_CONV=4. Rows R = BATCH*SEQ = 2048.
// ---------------------------------------------------------------------------

#define R_TOT   2048          // BATCH*SEQ
#define DM      1024
#define DI      2048
#define DTR     64
#define DST     16

// Scratch (device globals: allocation-free per harness rules)
__device__ float g_xn  [R_TOT * DM];        //  8 MB  normalized input
__device__ float g_xz  [R_TOT * 2 * DI];    // 32 MB  in_proj output (xc | z)
__device__ float g_u   [R_TOT * DI];        // 16 MB  conv+silu output
__device__ float g_proj[R_TOT * 96];        //  0.75MB x_proj output (dt_raw|B|C)
__device__ float g_dt  [R_TOT * DI];        // 16 MB  softplus(dt)
__device__ float g_y   [R_TOT * DI];        // 16 MB  scan output * silu(z)

// ---------------------------------------------------------------------------
// RMSNorm: one block per row
// ---------------------------------------------------------------------------
__global__ void rmsnorm_kernel(const float* __restrict__ x,
                               const float* __restrict__ w,
                               float* __restrict__ out)
{
    const int row = blockIdx.x;
    const int tid = threadIdx.x;
    const float* xr = x + (long)row * DM;

    float s = 0.f;
    #pragma unroll
    for (int i = 0; i < 4; i++) {
        float v = xr[tid + i * 256];
        s += v * v;
    }
    #pragma unroll
    for (int o = 16; o; o >>= 1) s += __shfl_xor_sync(0xffffffffu, s, o);

    __shared__ float sm[8];
    if ((tid & 31) == 0) sm[tid >> 5] = s;
    __syncthreads();
    float tot = sm[0] + sm[1] + sm[2] + sm[3] + sm[4] + sm[5] + sm[6] + sm[7];
    float scale = rsqrtf(tot * (1.f / DM) + 1e-6f);

    #pragma unroll
    for (int i = 0; i < 4; i++) {
        int c = tid + i * 256;
        out[(long)row * DM + c] = xr[c] * scale * w[c];
    }
}

// ---------------------------------------------------------------------------
// Generic SGEMM:  C[m,n] = sum_k A[m,k] * B[n,k]   (A: M x K row-major lda,
//                                                   B: N x K row-major ldb)
// 128x128 tile, BK=16, 256 threads, 8x8 per thread (split-half fragments).
// epi: 0 = none, 1 = softplus(acc + bias[n]), 2 = acc + resid[m,n]
// ---------------------------------------------------------------------------
__global__ void __launch_bounds__(256, 2)
gemm_nt(const float* __restrict__ A, int lda,
        const float* __restrict__ B, int ldb,
        float* __restrict__ C, int ldc,
        int M, int N, int K,
        int epi, const float* __restrict__ bias,
        const float* __restrict__ resid)
{
    __shared__ float As[16][132];
    __shared__ float Bs[16][132];

    const int tid   = threadIdx.x;
    const int m0    = blockIdx.y * 128;
    const int n0    = blockIdx.x * 128;
    const int kk    = tid & 15;     // k within tile for loads
    const int rbase = tid >> 4;     // row base for loads (0..15)
    const int tx    = tid & 15;     // n-fragment index
    const int ty    = tid >> 4;     // m-fragment index

    float acc[8][8];
    #pragma unroll
    for (int i = 0; i < 8; i++)
        #pragma unroll
        for (int j = 0; j < 8; j++) acc[i][j] = 0.f;

    float aReg[8], bReg[8];

    // prefetch tile 0
    #pragma unroll
    for (int i = 0; i < 8; i++) {
        int r  = rbase + i * 16;
        int gm = m0 + r;
        int gn = n0 + r;
        aReg[i] = (gm < M) ? A[(long)gm * lda + kk] : 0.f;
        bReg[i] = (gn < N) ? B[(long)gn * ldb + kk] : 0.f;
    }

    for (int k0 = 0; k0 < K; k0 += 16) {
        #pragma unroll
        for (int i = 0; i < 8; i++) {
            As[kk][rbase + i * 16] = aReg[i];
            Bs[kk][rbase + i * 16] = bReg[i];
        }
        __syncthreads();

        if (k0 + 16 < K) {
            const int kn = k0 + 16;
            #pragma unroll
            for (int i = 0; i < 8; i++) {
                int r  = rbase + i * 16;
                int gm = m0 + r;
                int gn = n0 + r;
                aReg[i] = (gm < M) ? A[(long)gm * lda + kn + kk] : 0.f;
                bReg[i] = (gn < N) ? B[(long)gn * ldb + kn + kk] : 0.f;
            }
        }

        #pragma unroll
        for (int k = 0; k < 16; k++) {
            float4 a0 = *(const float4*)&As[k][ty * 4];
            float4 a1 = *(const float4*)&As[k][64 + ty * 4];
            float4 b0 = *(const float4*)&Bs[k][tx * 4];
            float4 b1 = *(const float4*)&Bs[k][64 + tx * 4];
            float av[8] = {a0.x, a0.y, a0.z, a0.w, a1.x, a1.y, a1.z, a1.w};
            float bv[8] = {b0.x, b0.y, b0.z, b0.w, b1.x, b1.y, b1.z, b1.w};
            #pragma unroll
            for (int i = 0; i < 8; i++)
                #pragma unroll
                for (int j = 0; j < 8; j++)
                    acc[i][j] = fmaf(av[i], bv[j], acc[i][j]);
        }
        __syncthreads();
    }

    // epilogue
    #pragma unroll
    for (int i = 0; i < 8; i++) {
        int gm = m0 + ((i < 4) ? (ty * 4 + i) : (64 + ty * 4 + (i - 4)));
        if (gm >= M) continue;
        #pragma unroll
        for (int j = 0; j < 8; j++) {
            int gn = n0 + ((j < 4) ? (tx * 4 + j) : (64 + tx * 4 + (j - 4)));
            if (gn >= N) continue;
            float v = acc[i][j];
            if (epi == 1) {
                v += bias[gn];
                v = (v > 20.f) ? v : log1pf(__expf(v));
            } else if (epi == 2) {
                v += resid[(long)gm * ldc + gn];
            }
            C[(long)gm * ldc + gn] = v;
        }
    }
}

// ---------------------------------------------------------------------------
// Depthwise causal conv (taps=4) + SiLU.  xc = first DI cols of xz.
// ---------------------------------------------------------------------------
__global__ void conv_silu_kernel(const float* __restrict__ xz,
                                 const float* __restrict__ cw,
                                 const float* __restrict__ cb,
                                 float* __restrict__ u)
{
    int gid = blockIdx.x * blockDim.x + threadIdx.x;
    if (gid >= R_TOT * DI) return;
    int d   = gid & (DI - 1);
    int row = gid >> 11;
    int t   = row & 1023;

    float acc = cb[d];
    #pragma unroll
    for (int j = 0; j < 4; j++) {
        int tt = t - 3 + j;
        if (tt >= 0)
            acc = fmaf(xz[(long)(row - 3 + j) * (2 * DI) + d], cw[d * 4 + j], acc);
    }
    u[gid] = acc / (1.f + __expf(-acc));   // silu
}

// ---------------------------------------------------------------------------
// Selective scan. 16 lanes per (b,d) channel: lane = state index n.
// Fuses: y = (state . C + D*u) * silu(z)
// ---------------------------------------------------------------------------
__global__ void scan_kernel(const float* __restrict__ dt,
                            const float* __restrict__ u,
                            const float* __restrict__ proj,
                            const float* __restrict__ xz,
                            const float* __restrict__ A_log,
                            const float* __restrict__ D_diag,
                            float* __restrict__ y)
{
    const int tid  = threadIdx.x;
    const int n    = tid & 15;          // state index
    const int g    = tid >> 4;          // channel group within block (16)
    const int dblk = blockIdx.x & 127;
    const int b    = blockIdx.x >> 7;
    const int d    = dblk * 16 + g;

    const float Adn = -__expf(A_log[d * DST + n]);
    const float Dd  = D_diag[d];
    const float* projb = proj + (long)b * 1024 * 96;

    float state = 0.f;
    for (int t = 0; t < 1024; t++) {
        long row = (long)b * 1024 + t;
        float dtv = dt[row * DI + d];
        float uv  = u [row * DI + d];
        float Bv  = projb[t * 96 + 64 + n];
        float Cv  = projb[t * 96 + 80 + n];

        float dA = __expf(dtv * Adn);
        state = fmaf(dA, state, (dtv * uv) * Bv);

        float part = state * Cv;
        part += __shfl_xor_sync(0xffffffffu, part, 1);
        part += __shfl_xor_sync(0xffffffffu, part, 2);
        part += __shfl_xor_sync(0xffffffffu, part, 4);
        part += __shfl_xor_sync(0xffffffffu, part, 8);

        if (n == 0) {
            float zv = xz[row * (2 * DI) + DI + d];
            float sz = zv / (1.f + __expf(-zv));
            y[row * DI + d] = (part + Dd * uv) * sz;
        }
    }
}

// ---------------------------------------------------------------------------
// Launch
// ---------------------------------------------------------------------------
extern "C" void kernel_launch(void* const* d_in, const int* in_sizes, int n_in,
                              void* d_out, int out_size)
{
    const float* x          = (const float*)d_in[0];
    const float* norm_w     = (const float*)d_in[1];
    const float* in_proj_w  = (const float*)d_in[2];
    const float* conv_w     = (const float*)d_in[3];
    const float* conv_b     = (const float*)d_in[4];
    const float* x_proj_w   = (const float*)d_in[5];
    const float* dt_proj_w  = (const float*)d_in[6];
    const float* dt_proj_b  = (const float*)d_in[7];
    const float* A_log      = (const float*)d_in[8];
    const float* D_diag     = (const float*)d_in[9];
    const float* out_proj_w = (const float*)d_in[10];
    float* out = (float*)d_out;

    float *xn, *xz, *u, *proj, *dtb, *y;
    cudaGetSymbolAddress((void**)&xn,   g_xn);
    cudaGetSymbolAddress((void**)&xz,   g_xz);
    cudaGetSymbolAddress((void**)&u,    g_u);
    cudaGetSymbolAddress((void**)&proj, g_proj);
    cudaGetSymbolAddress((void**)&dtb,  g_dt);
    cudaGetSymbolAddress((void**)&y,    g_y);

    // 1) RMSNorm
    rmsnorm_kernel<<<R_TOT, 256>>>(x, norm_w, xn);

    // 2) in_proj: (2048x1024) @ (4096x1024)^T -> xz (2048x4096)
    gemm_nt<<<dim3(32, 16), 256>>>(xn, DM, in_proj_w, DM, xz, 2 * DI,
                                   R_TOT, 2 * DI, DM, 0, nullptr, nullptr);

    // 3) depthwise conv + silu -> u (2048x2048)
    conv_silu_kernel<<<(R_TOT * DI) / 256, 256>>>(xz, conv_w, conv_b, u);

    // 4) x_proj: (2048x2048) @ (96x2048)^T -> proj (2048x96)
    gemm_nt<<<dim3(1, 16), 256>>>(u, DI, x_proj_w, DI, proj, 96,
                                  R_TOT, 96, DI, 0, nullptr, nullptr);

    // 5) dt: softplus(proj[:, :64] @ (2048x64)^T + b) -> dt (2048x2048)
    gemm_nt<<<dim3(16, 16), 256>>>(proj, 96, dt_proj_w, DTR, dtb, DI,
                                   R_TOT, DI, DTR, 1, dt_proj_b, nullptr);

    // 6) selective scan (fused with *silu(z)) -> y (2048x2048)
    scan_kernel<<<256, 256>>>(dtb, u, proj, xz, A_log, D_diag, y);

    // 7) out_proj + residual: x + y @ (1024x2048)^T -> out (2048x1024)
    gemm_nt<<<dim3(8, 16), 256>>>(y, DI, out_proj_w, DI, out, DM,
                                  R_TOT, DM, DI, 2, nullptr, x);
}

// round 2
// speedup vs baseline: 1.5356x; 1.5356x over previous
#include <cuda_runtime.h>
#include <cuda_bf16.h>
#include <cstdint>

// ---------------------------------------------------------------------------
// Mamba block. GEMMs on tensor cores (tf32 mma.sync), scan/conv fp32.
// BATCH=2 SEQ=1024 D_MODEL=1024 D_INNER=2048 DT_RANK=64 D_STATE=16 D_CONV=4
// ---------------------------------------------------------------------------

#define R_TOT   2048
#define DM      1024
#define DI      2048
#define DTR     64
#define DST     16
#define XSPLIT  16

// Scratch
__device__ float g_xn   [R_TOT * DM];
__device__ float g_xz   [R_TOT * 2 * DI];
__device__ float g_u    [R_TOT * DI];
__device__ float g_projp[XSPLIT * R_TOT * 96];
__device__ float g_proj [R_TOT * 96];
__device__ float g_dt   [R_TOT * DI];
__device__ float g_y    [R_TOT * DI];

// ---------------------------------------------------------------------------
__device__ __forceinline__ uint32_t f2tf(float f) {
    uint32_t u;
    asm("cvt.rna.tf32.f32 %0, %1;" : "=r"(u) : "f"(f));
    return u;
}

#define LDSM_X4(r0, r1, r2, r3, addr)                                          \
    asm volatile("ldmatrix.sync.aligned.m8n8.x4.shared.b16 {%0,%1,%2,%3}, [%4];" \
                 : "=r"(r0), "=r"(r1), "=r"(r2), "=r"(r3) : "r"(addr))

#define MMA_TF32(d, a0, a1, a2, a3, b0, b1)                                    \
    asm volatile("mma.sync.aligned.m16n8k8.row.col.f32.tf32.tf32.f32 "         \
                 "{%0,%1,%2,%3}, {%4,%5,%6,%7}, {%8,%9}, {%0,%1,%2,%3};"       \
                 : "+f"(d[0]), "+f"(d[1]), "+f"(d[2]), "+f"(d[3])              \
                 : "r"(a0), "r"(a1), "r"(a2), "r"(a3), "r"(b0), "r"(b1))

// ---------------------------------------------------------------------------
// TF32 GEMM:  C[m,n] = sum_k A[m,k]*B[n,k]
// 128x128 tile, BK=32, 256 threads (8 warps, 2m x 4n), warp tile 64x32.
// Requires M%128==0, N%128==0, K%32==0, K>=64, lda/ldb allow float4 loads.
// epi: 0 none, 1 softplus(acc+bias[n]), 2 acc+resid[m,n]
// ---------------------------------------------------------------------------
__global__ void __launch_bounds__(256, 1)
gemm_tf32(const float* __restrict__ A, int lda,
          const float* __restrict__ B, int ldb,
          float* __restrict__ C, int ldc,
          int K, int epi,
          const float* __restrict__ bias,
          const float* __restrict__ resid)
{
    // padded stride 36 floats (144B): conflict-free ldmatrix + aligned STS.128
    __shared__ float sA[128 * 36];
    __shared__ float sB[128 * 36];

    const int tid  = threadIdx.x;
    const int lane = tid & 31;
    const int wid  = tid >> 5;
    const int wm   = wid >> 2;          // 0..1 -> m offset wm*64
    const int wn   = wid & 3;           // 0..3 -> n offset wn*32
    const int m0   = blockIdx.y * 128;
    const int n0   = blockIdx.x * 128;

    // global load mapping: 128 rows x 8 float4 cols, 4 passes
    const int lr = tid >> 3;            // 0..31
    const int lc = tid & 7;             // float4 col

    // smem byte bases
    const uint32_t aBase = (uint32_t)__cvta_generic_to_shared(sA);
    const uint32_t bBase = (uint32_t)__cvta_generic_to_shared(sB);

    // ldmatrix per-lane address components
    // A tile (16m x 8k as 16x16 b16): rows m + (lane&15), col +4 tf32 if lane>=16
    const int aRow  = wm * 64 + (lane & 15);
    const int aColO = (lane >> 4) << 2;           // 0 or 4
    const uint32_t aFragBase = aBase + (uint32_t)(aRow * 36 + aColO) * 4u;
    // B x4 covers 2 n-tiles (16n): rows n + (lane&7) + (lane&16)?8, col +4 if lane&8
    const int bRow  = wn * 32 + (lane & 7) + ((lane & 16) >> 1);
    const int bColO = (lane & 8) >> 1;            // 0 or 4
    const uint32_t bFragBase = bBase + (uint32_t)(bRow * 36 + bColO) * 4u;

    float acc[4][4][4];
    #pragma unroll
    for (int i = 0; i < 4; i++)
        #pragma unroll
        for (int j = 0; j < 4; j++)
            #pragma unroll
            for (int q = 0; q < 4; q++) acc[i][j][q] = 0.f;

    float4 aSt[4], bSt[4];

    // prefetch tile 0
    #pragma unroll
    for (int p = 0; p < 4; p++) {
        int row = lr + p * 32;
        aSt[p] = *(const float4*)(A + (size_t)(m0 + row) * lda + lc * 4);
        bSt[p] = *(const float4*)(B + (size_t)(n0 + row) * ldb + lc * 4);
    }

    for (int kt = 0; kt < K; kt += 32) {
        // stage to smem with tf32 rounding
        #pragma unroll
        for (int p = 0; p < 4; p++) {
            int row = lr + p * 32;
            uint4 av = make_uint4(f2tf(aSt[p].x), f2tf(aSt[p].y),
                                  f2tf(aSt[p].z), f2tf(aSt[p].w));
            uint4 bv = make_uint4(f2tf(bSt[p].x), f2tf(bSt[p].y),
                                  f2tf(bSt[p].z), f2tf(bSt[p].w));
            *(uint4*)&sA[row * 36 + lc * 4] = av;
            *(uint4*)&sB[row * 36 + lc * 4] = bv;
        }
        __syncthreads();

        if (kt + 32 < K) {
            const int kn = kt + 32;
            #pragma unroll
            for (int p = 0; p < 4; p++) {
                int row = lr + p * 32;
                aSt[p] = *(const float4*)(A + (size_t)(m0 + row) * lda + kn + lc * 4);
                bSt[p] = *(const float4*)(B + (size_t)(n0 + row) * ldb + kn + lc * 4);
            }
        }

        #pragma unroll
        for (int ks = 0; ks < 4; ks++) {
            uint32_t a[4][4];
            #pragma unroll
            for (int mi = 0; mi < 4; mi++) {
                uint32_t addr = aFragBase + (uint32_t)(mi * 16 * 36 + ks * 8) * 4u;
                LDSM_X4(a[mi][0], a[mi][1], a[mi][2], a[mi][3], addr);
            }
            uint32_t b[4][2];
            #pragma unroll
            for (int nj = 0; nj < 2; nj++) {
                uint32_t addr = bFragBase + (uint32_t)(nj * 16 * 36 + ks * 8) * 4u;
                LDSM_X4(b[2 * nj][0], b[2 * nj][1], b[2 * nj + 1][0], b[2 * nj + 1][1], addr);
            }
            #pragma unroll
            for (int mi = 0; mi < 4; mi++)
                #pragma unroll
                for (int ni = 0; ni < 4; ni++)
                    MMA_TF32(acc[mi][ni], a[mi][0], a[mi][1], a[mi][2], a[mi][3],
                             b[ni][0], b[ni][1]);
        }
        __syncthreads();
    }

    // epilogue
    const int er = lane >> 2;
    const int ec = (lane & 3) * 2;
    #pragma unroll
    for (int mi = 0; mi < 4; mi++) {
        int gm = m0 + wm * 64 + mi * 16 + er;
        #pragma unroll
        for (int ni = 0; ni < 4; ni++) {
            int gn = n0 + wn * 32 + ni * 8 + ec;
            #pragma unroll
            for (int half = 0; half < 2; half++) {
                int gmm = gm + half * 8;
                float v0 = acc[mi][ni][half * 2];
                float v1 = acc[mi][ni][half * 2 + 1];
                if (epi == 1) {
                    v0 += bias[gn];
                    v1 += bias[gn + 1];
                    v0 = (v0 > 20.f) ? v0 : log1pf(__expf(v0));
                    v1 = (v1 > 20.f) ? v1 : log1pf(__expf(v1));
                } else if (epi == 2) {
                    const float2 r = *(const float2*)(resid + (size_t)gmm * ldc + gn);
                    v0 += r.x;
                    v1 += r.y;
                }
                *(float2*)(C + (size_t)gmm * ldc + gn) = make_float2(v0, v1);
            }
        }
    }
}

// ---------------------------------------------------------------------------
// RMSNorm
// ---------------------------------------------------------------------------
__global__ void rmsnorm_kernel(const float* __restrict__ x,
                               const float* __restrict__ w,
                               float* __restrict__ out)
{
    const int row = blockIdx.x;
    const int tid = threadIdx.x;
    const float* xr = x + (long)row * DM;

    float s = 0.f;
    #pragma unroll
    for (int i = 0; i < 4; i++) {
        float v = xr[tid + i * 256];
        s += v * v;
    }
    #pragma unroll
    for (int o = 16; o; o >>= 1) s += __shfl_xor_sync(0xffffffffu, s, o);

    __shared__ float sm[8];
    if ((tid & 31) == 0) sm[tid >> 5] = s;
    __syncthreads();
    float tot = sm[0] + sm[1] + sm[2] + sm[3] + sm[4] + sm[5] + sm[6] + sm[7];
    float scale = rsqrtf(tot * (1.f / DM) + 1e-6f);

    #pragma unroll
    for (int i = 0; i < 4; i++) {
        int c = tid + i * 256;
        out[(long)row * DM + c] = xr[c] * scale * w[c];
    }
}

// ---------------------------------------------------------------------------
// Depthwise causal conv (4 taps) + SiLU
// ---------------------------------------------------------------------------
__global__ void conv_silu_kernel(const float* __restrict__ xz,
                                 const float* __restrict__ cw,
                                 const float* __restrict__ cb,
                                 float* __restrict__ u)
{
    int gid = blockIdx.x * blockDim.x + threadIdx.x;
    if (gid >= R_TOT * DI) return;
    int d   = gid & (DI - 1);
    int row = gid >> 11;
    int t   = row & 1023;

    float acc = cb[d];
    #pragma unroll
    for (int j = 0; j < 4; j++) {
        int tt = t - 3 + j;
        if (tt >= 0)
            acc = fmaf(xz[(long)(row - 3 + j) * (2 * DI) + d], cw[d * 4 + j], acc);
    }
    u[gid] = acc / (1.f + __expf(-acc));
}

// ---------------------------------------------------------------------------
// x_proj split-K: grid (16 m-tiles, XSPLIT k-splits). block 256.
// partial[s][m][n] = u[m, ks:ks+128] @ w[n, ks:ks+128]^T   (n<96)
// ---------------------------------------------------------------------------
__global__ void __launch_bounds__(256, 2)
xproj_splitk(const float* __restrict__ u,
             const float* __restrict__ w,
             float* __restrict__ partial)
{
    __shared__ float As[16][132];
    __shared__ float Bs[16][100];

    const int tid = threadIdx.x;
    const int m0  = blockIdx.x * 128;
    const int kc  = blockIdx.y * (DI / XSPLIT);   // 128-wide K chunk
    const int kk  = tid & 15;
    const int rp  = tid >> 4;
    const int ty  = tid >> 4;   // m frag base
    const int tx  = tid & 15;   // n frag base

    float acc[8][6];
    #pragma unroll
    for (int i = 0; i < 8; i++)
        #pragma unroll
        for (int j = 0; j < 6; j++) acc[i][j] = 0.f;

    for (int kt = 0; kt < DI / XSPLIT; kt += 16) {
        const int kb = kc + kt;
        #pragma unroll
        for (int p = 0; p < 8; p++)
            As[kk][rp + p * 16] = u[(size_t)(m0 + rp + p * 16) * DI + kb + kk];
        #pragma unroll
        for (int q = 0; q < 6; q++)
            Bs[kk][rp + q * 16] = w[(size_t)(rp + q * 16) * DI + kb + kk];
        __syncthreads();

        #pragma unroll
        for (int k = 0; k < 16; k++) {
            float av[8], bv[6];
            #pragma unroll
            for (int i = 0; i < 8; i++) av[i] = As[k][ty + i * 16];
            #pragma unroll
            for (int j = 0; j < 6; j++) bv[j] = Bs[k][tx + j * 16];
            #pragma unroll
            for (int i = 0; i < 8; i++)
                #pragma unroll
                for (int j = 0; j < 6; j++)
                    acc[i][j] = fmaf(av[i], bv[j], acc[i][j]);
        }
        __syncthreads();
    }

    float* outp = partial + (size_t)blockIdx.y * R_TOT * 96;
    #pragma unroll
    for (int i = 0; i < 8; i++)
        #pragma unroll
        for (int j = 0; j < 6; j++)
            outp[(size_t)(m0 + ty + i * 16) * 96 + tx + j * 16] = acc[i][j];
}

__global__ void xproj_reduce(const float* __restrict__ partial,
                             float* __restrict__ proj)
{
    int idx = blockIdx.x * blockDim.x + threadIdx.x;
    if (idx >= R_TOT * 96) return;
    float s = 0.f;
    #pragma unroll
    for (int p = 0; p < XSPLIT; p++)
        s += partial[(size_t)p * R_TOT * 96 + idx];
    proj[idx] = s;
}

// ---------------------------------------------------------------------------
// Selective scan (16 lanes per channel), fused *silu(z)
// ---------------------------------------------------------------------------
__global__ void scan_kernel(const float* __restrict__ dt,
                            const float* __restrict__ u,
                            const float* __restrict__ proj,
                            const float* __restrict__ xz,
                            const float* __restrict__ A_log,
                            const float* __restrict__ D_diag,
                            float* __restrict__ y)
{
    const int tid  = threadIdx.x;
    const int n    = tid & 15;
    const int g    = tid >> 4;
    const int dblk = blockIdx.x & 127;
    const int b    = blockIdx.x >> 7;
    const int d    = dblk * 16 + g;

    const float Adn = -__expf(A_log[d * DST + n]);
    const float Dd  = D_diag[d];
    const float* projb = proj + (size_t)b * 1024 * 96;

    float state = 0.f;
    for (int t = 0; t < 1024; t++) {
        size_t row = (size_t)b * 1024 + t;
        float dtv = dt[row * DI + d];
        float uv  = u [row * DI + d];
        float Bv  = projb[t * 96 + 64 + n];
        float Cv  = projb[t * 96 + 80 + n];

        float dA = __expf(dtv * Adn);
        state = fmaf(dA, state, (dtv * uv) * Bv);

        float part = state * Cv;
        part += __shfl_xor_sync(0xffffffffu, part, 1);
        part += __shfl_xor_sync(0xffffffffu, part, 2);
        part += __shfl_xor_sync(0xffffffffu, part, 4);
        part += __shfl_xor_sync(0xffffffffu, part, 8);

        if (n == 0) {
            float zv = xz[row * (2 * DI) + DI + d];
            float sz = zv / (1.f + __expf(-zv));
            y[row * DI + d] = (part + Dd * uv) * sz;
        }
    }
}

// ---------------------------------------------------------------------------
extern "C" void kernel_launch(void* const* d_in, const int* in_sizes, int n_in,
                              void* d_out, int out_size)
{
    const float* x          = (const float*)d_in[0];
    const float* norm_w     = (const float*)d_in[1];
    const float* in_proj_w  = (const float*)d_in[2];
    const float* conv_w     = (const float*)d_in[3];
    const float* conv_b     = (const float*)d_in[4];
    const float* x_proj_w   = (const float*)d_in[5];
    const float* dt_proj_w  = (const float*)d_in[6];
    const float* dt_proj_b  = (const float*)d_in[7];
    const float* A_log      = (const float*)d_in[8];
    const float* D_diag     = (const float*)d_in[9];
    const float* out_proj_w = (const float*)d_in[10];
    float* out = (float*)d_out;

    float *xn, *xz, *u, *projp, *proj, *dtb, *y;
    cudaGetSymbolAddress((void**)&xn,    g_xn);
    cudaGetSymbolAddress((void**)&xz,    g_xz);
    cudaGetSymbolAddress((void**)&u,     g_u);
    cudaGetSymbolAddress((void**)&projp, g_projp);
    cudaGetSymbolAddress((void**)&proj,  g_proj);
    cudaGetSymbolAddress((void**)&dtb,   g_dt);
    cudaGetSymbolAddress((void**)&y,     g_y);

    // 1) RMSNorm
    rmsnorm_kernel<<<R_TOT, 256>>>(x, norm_w, xn);

    // 2) in_proj (tf32): 2048 x 4096 x 1024
    gemm_tf32<<<dim3(32, 16), 256>>>(xn, DM, in_proj_w, DM, xz, 2 * DI,
                                     DM, 0, nullptr, nullptr);

    // 3) conv + silu
    conv_silu_kernel<<<(R_TOT * DI) / 256, 256>>>(xz, conv_w, conv_b, u);

    // 4) x_proj split-K + reduce: 2048 x 96 x 2048
    xproj_splitk<<<dim3(16, XSPLIT), 256>>>(u, x_proj_w, projp);
    xproj_reduce<<<(R_TOT * 96 + 255) / 256, 256>>>(projp, proj);

    // 5) dt (tf32): softplus(proj[:, :64] @ dt_proj_w^T + b): 2048 x 2048 x 64
    gemm_tf32<<<dim3(16, 16), 256>>>(proj, 96, dt_proj_w, DTR, dtb, DI,
                                     DTR, 1, dt_proj_b, nullptr);

    // 6) selective scan
    scan_kernel<<<256, 256>>>(dtb, u, proj, xz, A_log, D_diag, y);

    // 7) out_proj + residual (tf32): 2048 x 1024 x 2048
    gemm_tf32<<<dim3(8, 16), 256>>>(y, DI, out_proj_w, DI, out, DM,
                                    DI, 2, nullptr, x);
}

// round 3
// speedup vs baseline: 4.1317x; 2.6907x over previous
#include <cuda_runtime.h>
#include <cuda_bf16.h>
#include <cstdint>

// ---------------------------------------------------------------------------
// Mamba block. Big GEMMs: bf16 mma.sync m16n8k16 (fp32 accum), double-buffered.
// Scan: smem-staged, coalesced. BATCH=2 SEQ=1024 DM=1024 DI=2048 DTR=64 DST=16
// ---------------------------------------------------------------------------

#define R_TOT   2048
#define DM      1024
#define DI      2048
#define DTR     64
#define DST     16
#define XSPLIT  16
#define TC      64          // scan time-chunk

// Scratch
__device__ float g_xn   [R_TOT * DM];
__device__ float g_xz   [R_TOT * 2 * DI];
__device__ float g_u    [R_TOT * DI];
__device__ float g_projp[XSPLIT * R_TOT * 96];
__device__ float g_proj [R_TOT * 96];
__device__ float g_dt   [R_TOT * DI];
__device__ float g_y    [R_TOT * DI];

#define LDSM_X4(r0, r1, r2, r3, addr)                                          \
    asm volatile("ldmatrix.sync.aligned.m8n8.x4.shared.b16 {%0,%1,%2,%3}, [%4];" \
                 : "=r"(r0), "=r"(r1), "=r"(r2), "=r"(r3) : "r"(addr))

#define MMA_BF16(d, a0, a1, a2, a3, b0, b1)                                    \
    asm volatile("mma.sync.aligned.m16n8k16.row.col.f32.bf16.bf16.f32 "        \
                 "{%0,%1,%2,%3}, {%4,%5,%6,%7}, {%8,%9}, {%0,%1,%2,%3};"       \
                 : "+f"(d[0]), "+f"(d[1]), "+f"(d[2]), "+f"(d[3])              \
                 : "r"(a0), "r"(a1), "r"(a2), "r"(a3), "r"(b0), "r"(b1))

__device__ __forceinline__ uint32_t pack_bf2(float x, float y) {
    __nv_bfloat162 h = __floats2bfloat162_rn(x, y);
    return *(uint32_t*)&h;
}

// ---------------------------------------------------------------------------
// BF16 GEMM:  C[m,n] = sum_k A[m,k]*B[n,k]  (A,B fp32 in gmem, cvt on stage)
// 128x128 tile, BK=32, 256 thr (8 warps: 2m x 4n), warp 64x32, 2-stage smem.
// Requires M%128==0, N%128==0, K%32==0, 16B-aligned rows.
// epi: 0 none, 1 softplus(acc+bias[n]), 2 acc+resid[m,n]
// ---------------------------------------------------------------------------
#define SSTRIDE 40                      // halves per smem row (80B, ldmatrix-safe)
__global__ void __launch_bounds__(256)
gemm_bf16(const float* __restrict__ A, int lda,
          const float* __restrict__ B, int ldb,
          float* __restrict__ C, int ldc,
          int K, int epi,
          const float* __restrict__ bias,
          const float* __restrict__ resid)
{
    __shared__ __nv_bfloat16 sA[2][128 * SSTRIDE];
    __shared__ __nv_bfloat16 sB[2][128 * SSTRIDE];

    const int tid  = threadIdx.x;
    const int lane = tid & 31;
    const int wid  = tid >> 5;
    const int wm   = wid >> 2;
    const int wn   = wid & 3;
    const int m0   = blockIdx.y * 128;
    const int n0   = blockIdx.x * 128;

    // global staging map: rows lr,lr+64 ; float4 slots lc,lc+4
    const int lr = tid >> 2;
    const int lc = tid & 3;

    const uint32_t aBase = (uint32_t)__cvta_generic_to_shared(&sA[0][0]);
    const uint32_t bBase = (uint32_t)__cvta_generic_to_shared(&sB[0][0]);
    const uint32_t stageB = 128 * SSTRIDE * 2;   // bytes per stage

    // fragment ldmatrix lane addresses
    const int aRow = wm * 64 + (lane & 15);
    const uint32_t aFrag = aBase + (uint32_t)(aRow * SSTRIDE + (lane >> 4) * 8) * 2u;
    const int bRow = wn * 32 + (lane & 7) + ((lane & 16) >> 1);
    const uint32_t bFrag = bBase + (uint32_t)(bRow * SSTRIDE + (lane & 8)) * 2u;

    float acc[4][4][4];
    #pragma unroll
    for (int i = 0; i < 4; i++)
        #pragma unroll
        for (int j = 0; j < 4; j++)
            #pragma unroll
            for (int q = 0; q < 4; q++) acc[i][j][q] = 0.f;

    float4 aLd[2][2], bLd[2][2];

    // ---- LDG tile 0
    #pragma unroll
    for (int p = 0; p < 2; p++)
        #pragma unroll
        for (int q = 0; q < 2; q++) {
            aLd[p][q] = *(const float4*)(A + (size_t)(m0 + lr + p * 64) * lda + (lc + q * 4) * 4);
            bLd[p][q] = *(const float4*)(B + (size_t)(n0 + lr + p * 64) * ldb + (lc + q * 4) * 4);
        }
    // ---- STS stage 0
    #pragma unroll
    for (int p = 0; p < 2; p++)
        #pragma unroll
        for (int q = 0; q < 2; q++) {
            int row = lr + p * 64, sl = lc + q * 4;
            uint2 av = make_uint2(pack_bf2(aLd[p][q].x, aLd[p][q].y),
                                  pack_bf2(aLd[p][q].z, aLd[p][q].w));
            uint2 bv = make_uint2(pack_bf2(bLd[p][q].x, bLd[p][q].y),
                                  pack_bf2(bLd[p][q].z, bLd[p][q].w));
            *(uint2*)&sA[0][row * SSTRIDE + sl * 4] = av;
            *(uint2*)&sB[0][row * SSTRIDE + sl * 4] = bv;
        }
    __syncthreads();

    int s = 0;
    for (int kt = 0; kt < K; kt += 32) {
        const bool more = (kt + 32) < K;
        if (more) {
            const int kn = kt + 32;
            #pragma unroll
            for (int p = 0; p < 2; p++)
                #pragma unroll
                for (int q = 0; q < 2; q++) {
                    aLd[p][q] = *(const float4*)(A + (size_t)(m0 + lr + p * 64) * lda + kn + (lc + q * 4) * 4);
                    bLd[p][q] = *(const float4*)(B + (size_t)(n0 + lr + p * 64) * ldb + kn + (lc + q * 4) * 4);
                }
        }

        // ---- compute from stage s: 2 k-steps of k16
        const uint32_t aS = aFrag + (uint32_t)s * stageB;
        const uint32_t bS = bFrag + (uint32_t)s * stageB;
        #pragma unroll
        for (int ks = 0; ks < 2; ks++) {
            uint32_t a[4][4];
            #pragma unroll
            for (int mi = 0; mi < 4; mi++)
                LDSM_X4(a[mi][0], a[mi][1], a[mi][2], a[mi][3],
                        aS + (uint32_t)(mi * 16 * SSTRIDE + ks * 16) * 2u);
            uint32_t b[4][2];
            #pragma unroll
            for (int nj = 0; nj < 2; nj++) {
                uint32_t r0, r1, r2, r3;
                LDSM_X4(r0, r1, r2, r3,
                        bS + (uint32_t)(nj * 16 * SSTRIDE + ks * 16) * 2u);
                b[2 * nj][0] = r0; b[2 * nj][1] = r1;
                b[2 * nj + 1][0] = r2; b[2 * nj + 1][1] = r3;
            }
            #pragma unroll
            for (int mi = 0; mi < 4; mi++)
                #pragma unroll
                for (int ni = 0; ni < 4; ni++)
                    MMA_BF16(acc[mi][ni], a[mi][0], a[mi][1], a[mi][2], a[mi][3],
                             b[ni][0], b[ni][1]);
        }

        if (more) {
            const int so = s ^ 1;
            #pragma unroll
            for (int p = 0; p < 2; p++)
                #pragma unroll
                for (int q = 0; q < 2; q++) {
                    int row = lr + p * 64, sl = lc + q * 4;
                    uint2 av = make_uint2(pack_bf2(aLd[p][q].x, aLd[p][q].y),
                                          pack_bf2(aLd[p][q].z, aLd[p][q].w));
                    uint2 bv = make_uint2(pack_bf2(bLd[p][q].x, bLd[p][q].y),
                                          pack_bf2(bLd[p][q].z, bLd[p][q].w));
                    *(uint2*)&sA[so][row * SSTRIDE + sl * 4] = av;
                    *(uint2*)&sB[so][row * SSTRIDE + sl * 4] = bv;
                }
        }
        __syncthreads();
        s ^= 1;
    }

    // ---- epilogue
    const int er = lane >> 2;
    const int ec = (lane & 3) * 2;
    #pragma unroll
    for (int mi = 0; mi < 4; mi++) {
        int gm = m0 + wm * 64 + mi * 16 + er;
        #pragma unroll
        for (int ni = 0; ni < 4; ni++) {
            int gn = n0 + wn * 32 + ni * 8 + ec;
            #pragma unroll
            for (int half = 0; half < 2; half++) {
                int gmm = gm + half * 8;
                float v0 = acc[mi][ni][half * 2];
                float v1 = acc[mi][ni][half * 2 + 1];
                if (epi == 1) {
                    v0 += bias[gn];
                    v1 += bias[gn + 1];
                    v0 = (v0 > 20.f) ? v0 : log1pf(__expf(v0));
                    v1 = (v1 > 20.f) ? v1 : log1pf(__expf(v1));
                } else if (epi == 2) {
                    const float2 r = *(const float2*)(resid + (size_t)gmm * ldc + gn);
                    v0 += r.x;
                    v1 += r.y;
                }
                *(float2*)(C + (size_t)gmm * ldc + gn) = make_float2(v0, v1);
            }
        }
    }
}

// ---------------------------------------------------------------------------
// RMSNorm
// ---------------------------------------------------------------------------
__global__ void rmsnorm_kernel(const float* __restrict__ x,
                               const float* __restrict__ w,
                               float* __restrict__ out)
{
    const int row = blockIdx.x;
    const int tid = threadIdx.x;
    const float* xr = x + (long)row * DM;

    float s = 0.f;
    #pragma unroll
    for (int i = 0; i < 4; i++) {
        float v = xr[tid + i * 256];
        s += v * v;
    }
    #pragma unroll
    for (int o = 16; o; o >>= 1) s += __shfl_xor_sync(0xffffffffu, s, o);

    __shared__ float sm[8];
    if ((tid & 31) == 0) sm[tid >> 5] = s;
    __syncthreads();
    float tot = sm[0] + sm[1] + sm[2] + sm[3] + sm[4] + sm[5] + sm[6] + sm[7];
    float scale = rsqrtf(tot * (1.f / DM) + 1e-6f);

    #pragma unroll
    for (int i = 0; i < 4; i++) {
        int c = tid + i * 256;
        out[(long)row * DM + c] = xr[c] * scale * w[c];
    }
}

// ---------------------------------------------------------------------------
// Depthwise causal conv (4 taps) + SiLU
// ---------------------------------------------------------------------------
__global__ void conv_silu_kernel(const float* __restrict__ xz,
                                 const float* __restrict__ cw,
                                 const float* __restrict__ cb,
                                 float* __restrict__ u)
{
    int gid = blockIdx.x * blockDim.x + threadIdx.x;
    if (gid >= R_TOT * DI) return;
    int d   = gid & (DI - 1);
    int row = gid >> 11;
    int t   = row & 1023;

    float acc = cb[d];
    #pragma unroll
    for (int j = 0; j < 4; j++) {
        int tt = t - 3 + j;
        if (tt >= 0)
            acc = fmaf(xz[(long)(row - 3 + j) * (2 * DI) + d], cw[d * 4 + j], acc);
    }
    u[gid] = acc / (1.f + __expf(-acc));
}

// ---------------------------------------------------------------------------
// x_proj split-K (fp32) + reduce
// ---------------------------------------------------------------------------
__global__ void __launch_bounds__(256, 2)
xproj_splitk(const float* __restrict__ u,
             const float* __restrict__ w,
             float* __restrict__ partial)
{
    __shared__ float As[16][132];
    __shared__ float Bs[16][100];

    const int tid = threadIdx.x;
    const int m0  = blockIdx.x * 128;
    const int kc  = blockIdx.y * (DI / XSPLIT);
    const int kk  = tid & 15;
    const int rp  = tid >> 4;
    const int ty  = tid >> 4;
    const int tx  = tid & 15;

    float acc[8][6];
    #pragma unroll
    for (int i = 0; i < 8; i++)
        #pragma unroll
        for (int j = 0; j < 6; j++) acc[i][j] = 0.f;

    for (int kt = 0; kt < DI / XSPLIT; kt += 16) {
        const int kb = kc + kt;
        #pragma unroll
        for (int p = 0; p < 8; p++)
            As[kk][rp + p * 16] = u[(size_t)(m0 + rp + p * 16) * DI + kb + kk];
        #pragma unroll
        for (int q = 0; q < 6; q++)
            Bs[kk][rp + q * 16] = w[(size_t)(rp + q * 16) * DI + kb + kk];
        __syncthreads();

        #pragma unroll
        for (int k = 0; k < 16; k++) {
            float av[8], bv[6];
            #pragma unroll
            for (int i = 0; i < 8; i++) av[i] = As[k][ty + i * 16];
            #pragma unroll
            for (int j = 0; j < 6; j++) bv[j] = Bs[k][tx + j * 16];
            #pragma unroll
            for (int i = 0; i < 8; i++)
                #pragma unroll
                for (int j = 0; j < 6; j++)
                    acc[i][j] = fmaf(av[i], bv[j], acc[i][j]);
        }
        __syncthreads();
    }

    float* outp = partial + (size_t)blockIdx.y * R_TOT * 96;
    #pragma unroll
    for (int i = 0; i < 8; i++)
        #pragma unroll
        for (int j = 0; j < 6; j++)
            outp[(size_t)(m0 + ty + i * 16) * 96 + tx + j * 16] = acc[i][j];
}

__global__ void xproj_reduce(const float* __restrict__ partial,
                             float* __restrict__ proj)
{
    int idx = blockIdx.x * blockDim.x + threadIdx.x;
    if (idx >= R_TOT * 96) return;
    float s = 0.f;
    #pragma unroll
    for (int p = 0; p < XSPLIT; p++)
        s += partial[(size_t)p * R_TOT * 96 + idx];
    proj[idx] = s;
}

// ---------------------------------------------------------------------------
// Selective scan, smem-staged chunks of TC timesteps.
// Block: 16 channels x 16 states. Fused *silu(z).
// ---------------------------------------------------------------------------
__global__ void __launch_bounds__(256)
scan_kernel(const float* __restrict__ dt,
            const float* __restrict__ u,
            const float* __restrict__ proj,
            const float* __restrict__ xz,
            const float* __restrict__ A_log,
            const float* __restrict__ D_diag,
            float* __restrict__ y)
{
    __shared__ float s_dt[TC][16];
    __shared__ float s_u [TC][16];
    __shared__ float s_z [TC][16];
    __shared__ float s_bc[TC][32];
    __shared__ float s_y [TC][16];

    const int tid  = threadIdx.x;
    const int n    = tid & 15;
    const int g    = tid >> 4;
    const int dblk = blockIdx.x & 127;
    const int b    = blockIdx.x >> 7;
    const int d0   = dblk * 16;
    const int d    = d0 + g;
    const int bbase = b * 1024;

    const float Adn = -__expf(A_log[d * DST + n]);
    const float Dd  = D_diag[d];

    const int lr  = tid >> 2;
    const int lc4 = (tid & 3) * 4;

    float state = 0.f;
    for (int c = 0; c < 1024 / TC; c++) {
        const int t0 = c * TC;
        const size_t grow = (size_t)(bbase + t0 + lr);

        *(float4*)&s_dt[lr][lc4] = *(const float4*)(dt + grow * DI + d0 + lc4);
        *(float4*)&s_u [lr][lc4] = *(const float4*)(u  + grow * DI + d0 + lc4);
        *(float4*)&s_z [lr][lc4] = *(const float4*)(xz + grow * (2 * DI) + DI + d0 + lc4);
        #pragma unroll
        for (int p = 0; p < 2; p++) {
            int idx = tid + p * 256;
            int r2  = idx >> 3;
            int c8  = (idx & 7) * 4;
            *(float4*)&s_bc[r2][c8] =
                *(const float4*)(proj + (size_t)(bbase + t0 + r2) * 96 + 64 + c8);
        }
        __syncthreads();

        #pragma unroll 4
        for (int t = 0; t < TC; t++) {
            float dtv = s_dt[t][g];
            float uv  = s_u [t][g];
            float Bv  = s_bc[t][n];
            float Cv  = s_bc[t][16 + n];

            float dA = __expf(dtv * Adn);
            state = fmaf(dA, state, (dtv * uv) * Bv);

            float part = state * Cv;
            part += __shfl_xor_sync(0xffffffffu, part, 1);
            part += __shfl_xor_sync(0xffffffffu, part, 2);
            part += __shfl_xor_sync(0xffffffffu, part, 4);
            part += __shfl_xor_sync(0xffffffffu, part, 8);

            if (n == 0) {
                float zv = s_z[t][g];
                float sz = zv / (1.f + __expf(-zv));
                s_y[t][g] = (part + Dd * uv) * sz;
            }
        }
        __syncthreads();

        *(float4*)(y + grow * DI + d0 + lc4) = *(const float4*)&s_y[lr][lc4];
    }
}

// ---------------------------------------------------------------------------
extern "C" void kernel_launch(void* const* d_in, const int* in_sizes, int n_in,
                              void* d_out, int out_size)
{
    const float* x          = (const float*)d_in[0];
    const float* norm_w     = (const float*)d_in[1];
    const float* in_proj_w  = (const float*)d_in[2];
    const float* conv_w     = (const float*)d_in[3];
    const float* conv_b     = (const float*)d_in[4];
    const float* x_proj_w   = (const float*)d_in[5];
    const float* dt_proj_w  = (const float*)d_in[6];
    const float* dt_proj_b  = (const float*)d_in[7];
    const float* A_log      = (const float*)d_in[8];
    const float* D_diag     = (const float*)d_in[9];
    const float* out_proj_w = (const float*)d_in[10];
    float* out = (float*)d_out;

    float *xn, *xz, *u, *projp, *proj, *dtb, *y;
    cudaGetSymbolAddress((void**)&xn,    g_xn);
    cudaGetSymbolAddress((void**)&xz,    g_xz);
    cudaGetSymbolAddress((void**)&u,     g_u);
    cudaGetSymbolAddress((void**)&projp, g_projp);
    cudaGetSymbolAddress((void**)&proj,  g_proj);
    cudaGetSymbolAddress((void**)&dtb,   g_dt);
    cudaGetSymbolAddress((void**)&y,     g_y);

    // 1) RMSNorm
    rmsnorm_kernel<<<R_TOT, 256>>>(x, norm_w, xn);

    // 2) in_proj (bf16 TC): 2048 x 4096 x 1024
    gemm_bf16<<<dim3(32, 16), 256>>>(xn, DM, in_proj_w, DM, xz, 2 * DI,
                                     DM, 0, nullptr, nullptr);

    // 3) conv + silu
    conv_silu_kernel<<<(R_TOT * DI) / 256, 256>>>(xz, conv_w, conv_b, u);

    // 4) x_proj split-K + reduce: 2048 x 96 x 2048
    xproj_splitk<<<dim3(16, XSPLIT), 256>>>(u, x_proj_w, projp);
    xproj_reduce<<<(R_TOT * 96 + 255) / 256, 256>>>(projp, proj);

    // 5) dt (bf16 TC): softplus(proj[:, :64] @ dt_proj_w^T + b): 2048x2048x64
    gemm_bf16<<<dim3(16, 16), 256>>>(proj, 96, dt_proj_w, DTR, dtb, DI,
                                     DTR, 1, dt_proj_b, nullptr);

    // 6) selective scan
    scan_kernel<<<256, 256>>>(dtb, u, proj, xz, A_log, D_diag, y);

    // 7) out_proj + residual (bf16 TC): 2048 x 1024 x 2048
    gemm_bf16<<<dim3(8, 16), 256>>>(y, DI, out_proj_w, DI, out, DM,
                                    DI, 2, nullptr, x);
}

// round 6
// speedup vs baseline: 4.3431x; 1.0512x over previous
#include <cuda_runtime.h>
#include <cuda_bf16.h>
#include <cstdint>

// ---------------------------------------------------------------------------
// Mamba block. GEMMs: bf16 mma.sync m16n8k16 + cp.async 3-stage pipeline.
// Operands pre-converted to bf16. BATCH=2 SEQ=1024 DM=1024 DI=2048 DTR=64
// ---------------------------------------------------------------------------

#define R_TOT   2048
#define DM      1024
#define DI      2048
#define DTR     64
#define DST     16
#define XSPLIT  16
#define TCH     64          // scan time-chunk

// fp32 scratch
__device__ float g_xz   [R_TOT * 2 * DI];
__device__ float g_u    [R_TOT * DI];
__device__ float g_projp[XSPLIT * R_TOT * 96];
__device__ float g_proj [R_TOT * 96];
__device__ float g_dt   [R_TOT * DI];
// bf16 scratch (GEMM operands)
__device__ __nv_bfloat16 g_xnb [R_TOT * DM];
__device__ __nv_bfloat16 g_pjb [R_TOT * 96];
__device__ __nv_bfloat16 g_yb  [R_TOT * DI];
__device__ __nv_bfloat16 g_w1b [2 * DI * DM];    // in_proj_w
__device__ __nv_bfloat16 g_w2b [DI * DTR];       // dt_proj_w
__device__ __nv_bfloat16 g_w3b [DM * DI];        // out_proj_w

// ---------------------------------------------------------------------------
__device__ __forceinline__ uint32_t smem_u32(const void* p) {
    uint32_t a;
    asm("{ .reg .u64 t; cvta.to.shared.u64 t, %1; cvt.u32.u64 %0, t; }"
        : "=r"(a) : "l"(p));
    return a;
}
__device__ __forceinline__ uint32_t pack_bf2(float x, float y) {
    __nv_bfloat162 h = __floats2bfloat162_rn(x, y);
    return *(uint32_t*)&h;
}

#define LDSM_X4(r0, r1, r2, r3, addr)                                          \
    asm volatile("ldmatrix.sync.aligned.m8n8.x4.shared.b16 {%0,%1,%2,%3}, [%4];" \
                 : "=r"(r0), "=r"(r1), "=r"(r2), "=r"(r3) : "r"(addr))

#define MMA_BF16(d, a0, a1, a2, a3, b0, b1)                                    \
    asm volatile("mma.sync.aligned.m16n8k16.row.col.f32.bf16.bf16.f32 "        \
                 "{%0,%1,%2,%3}, {%4,%5,%6,%7}, {%8,%9}, {%0,%1,%2,%3};"       \
                 : "+f"(d[0]), "+f"(d[1]), "+f"(d[2]), "+f"(d[3])              \
                 : "r"(a0), "r"(a1), "r"(a2), "r"(a3), "r"(b0), "r"(b1))

#define CP16(saddr, gptr)                                                      \
    asm volatile("cp.async.cg.shared.global [%0], [%1], 16;"                   \
                 :: "r"(saddr), "l"(gptr))
#define CP_COMMIT() asm volatile("cp.async.commit_group;" ::: "memory")
#define CP_WAIT0()  asm volatile("cp.async.wait_group 0;" ::: "memory")
#define CP_WAIT1()  asm volatile("cp.async.wait_group 1;" ::: "memory")

// ---------------------------------------------------------------------------
// bf16 GEMM, cp.async 3-stage:  C[m,n] = sum_k A[m,k]*B[n,k]
// A: M x K bf16 (lda halves), B: N x K bf16 (ldb halves). 128x128 tile, BK=32.
// 256 thr (8 warps 2m x 4n). M,N mult of 128; K mult of 32; lda,ldb mult of 8.
// epi: 0 plain, 1 softplus(acc+bias[n]), 2 acc+resid
// ---------------------------------------------------------------------------
#define SST     40                    // halves per smem row (80B)
#define ASZ     (128 * SST * 2)       // 10240 B
#define STG     (2 * ASZ)             // 20480 B per stage
#define SMEM_DYN (3 * STG)            // 61440 B

__global__ void __launch_bounds__(256, 2)
gemm_cp(const __nv_bfloat16* __restrict__ A, int lda,
        const __nv_bfloat16* __restrict__ B, int ldb,
        float* __restrict__ C, int ldc,
        int K, int epi,
        const float* __restrict__ bias,
        const float* __restrict__ resid)
{
    extern __shared__ char smem[];
    const uint32_t sbase = smem_u32(smem);
    const int tid  = threadIdx.x;
    const int lane = tid & 31;
    const int wid  = tid >> 5;
    const int wm   = wid >> 2;
    const int wn   = wid & 3;
    const int m0   = blockIdx.y * 128;
    const int n0   = blockIdx.x * 128;

    // cp.async map: row = tid>>1; two 16B chunks at half-cols colh, colh+8
    const int row  = tid >> 1;
    const int colh = (tid & 1) * 16;
    const __nv_bfloat16* aP = A + (size_t)(m0 + row) * lda + colh;
    const __nv_bfloat16* bP = B + (size_t)(n0 + row) * ldb + colh;
    const uint32_t aS = sbase + (uint32_t)(row * SST + colh) * 2u;
    const uint32_t bS = aS + ASZ;

    // ldmatrix fragment bases
    const int aRow = wm * 64 + (lane & 15);
    const uint32_t aFrag = sbase + (uint32_t)(aRow * SST + (lane >> 4) * 8) * 2u;
    const int bRow = wn * 32 + (lane & 7) + ((lane & 16) >> 1);
    const uint32_t bFrag = sbase + ASZ + (uint32_t)(bRow * SST + (lane & 8)) * 2u;

    float acc[4][4][4];
    #pragma unroll
    for (int i = 0; i < 4; i++)
        #pragma unroll
        for (int j = 0; j < 4; j++)
            #pragma unroll
            for (int q = 0; q < 4; q++) acc[i][j][q] = 0.f;

    const int iters = K >> 5;

    // prologue: issue up to 2 stages
    int issued = 0;
    #pragma unroll
    for (int p = 0; p < 2; p++) {
        if (p < iters) {
            const uint32_t so = (uint32_t)p * STG;
            CP16(aS + so,      aP + p * 32);
            CP16(aS + so + 16, aP + p * 32 + 8);
            CP16(bS + so,      bP + p * 32);
            CP16(bS + so + 16, bP + p * 32 + 8);
            CP_COMMIT();
            issued++;
        }
    }

    for (int it = 0; it < iters; it++) {
        if (it == iters - 1) { CP_WAIT0(); } else { CP_WAIT1(); }
        __syncthreads();

        if (issued < iters) {
            const int st = issued;
            const uint32_t so = (uint32_t)(st % 3) * STG;
            CP16(aS + so,      aP + st * 32);
            CP16(aS + so + 16, aP + st * 32 + 8);
            CP16(bS + so,      bP + st * 32);
            CP16(bS + so + 16, bP + st * 32 + 8);
            CP_COMMIT();
            issued++;
        }

        const uint32_t so = (uint32_t)(it % 3) * STG;
        #pragma unroll
        for (int ks = 0; ks < 2; ks++) {
            uint32_t a[4][4];
            #pragma unroll
            for (int mi = 0; mi < 4; mi++)
                LDSM_X4(a[mi][0], a[mi][1], a[mi][2], a[mi][3],
                        aFrag + so + (uint32_t)(mi * 16 * SST + ks * 16) * 2u);
            uint32_t b[4][2];
            #pragma unroll
            for (int nj = 0; nj < 2; nj++) {
                uint32_t r0, r1, r2, r3;
                LDSM_X4(r0, r1, r2, r3,
                        bFrag + so + (uint32_t)(nj * 16 * SST + ks * 16) * 2u);
                b[2 * nj][0] = r0; b[2 * nj][1] = r1;
                b[2 * nj + 1][0] = r2; b[2 * nj + 1][1] = r3;
            }
            #pragma unroll
            for (int mi = 0; mi < 4; mi++)
                #pragma unroll
                for (int ni = 0; ni < 4; ni++)
                    MMA_BF16(acc[mi][ni], a[mi][0], a[mi][1], a[mi][2], a[mi][3],
                             b[ni][0], b[ni][1]);
        }
    }

    // epilogue
    const int er = lane >> 2;
    const int ec = (lane & 3) * 2;
    #pragma unroll
    for (int mi = 0; mi < 4; mi++) {
        int gm = m0 + wm * 64 + mi * 16 + er;
        #pragma unroll
        for (int ni = 0; ni < 4; ni++) {
            int gn = n0 + wn * 32 + ni * 8 + ec;
            #pragma unroll
            for (int half = 0; half < 2; half++) {
                int gmm = gm + half * 8;
                float v0 = acc[mi][ni][half * 2];
                float v1 = acc[mi][ni][half * 2 + 1];
                if (epi == 1) {
                    v0 += bias[gn];
                    v1 += bias[gn + 1];
                    v0 = (v0 > 20.f) ? v0 : log1pf(__expf(v0));
                    v1 = (v1 > 20.f) ? v1 : log1pf(__expf(v1));
                } else if (epi == 2) {
                    const float2 r = *(const float2*)(resid + (size_t)gmm * ldc + gn);
                    v0 += r.x;
                    v1 += r.y;
                }
                *(float2*)(C + (size_t)gmm * ldc + gn) = make_float2(v0, v1);
            }
        }
    }
}

// ---------------------------------------------------------------------------
// fp32 -> bf16 (vectorized), n % 4 == 0
// ---------------------------------------------------------------------------
__global__ void cvt_bf16_kernel(const float* __restrict__ in,
                                __nv_bfloat16* __restrict__ out, int n4)
{
    int i = blockIdx.x * blockDim.x + threadIdx.x;
    if (i >= n4) return;
    float4 v = *(const float4*)(in + (size_t)i * 4);
    uint2 o = make_uint2(pack_bf2(v.x, v.y), pack_bf2(v.z, v.w));
    *(uint2*)(out + (size_t)i * 4) = o;
}

// ---------------------------------------------------------------------------
// RMSNorm -> bf16 output
// ---------------------------------------------------------------------------
__global__ void rmsnorm_kernel(const float* __restrict__ x,
                               const float* __restrict__ w,
                               __nv_bfloat16* __restrict__ out)
{
    const int row = blockIdx.x;
    const int tid = threadIdx.x;
    const float* xr = x + (size_t)row * DM;

    float4 v = *(const float4*)(xr + tid * 4);
    float s = v.x * v.x + v.y * v.y + v.z * v.z + v.w * v.w;
    #pragma unroll
    for (int o = 16; o; o >>= 1) s += __shfl_xor_sync(0xffffffffu, s, o);

    __shared__ float sm[8];
    if ((tid & 31) == 0) sm[tid >> 5] = s;
    __syncthreads();
    float tot = sm[0] + sm[1] + sm[2] + sm[3] + sm[4] + sm[5] + sm[6] + sm[7];
    float scale = rsqrtf(tot * (1.f / DM) + 1e-6f);

    float4 wv = *(const float4*)(w + tid * 4);
    uint2 o = make_uint2(pack_bf2(v.x * scale * wv.x, v.y * scale * wv.y),
                         pack_bf2(v.z * scale * wv.z, v.w * scale * wv.w));
    *(uint2*)(out + (size_t)row * DM + tid * 4) = o;
}

// ---------------------------------------------------------------------------
// Depthwise causal conv (4 taps) + SiLU
// ---------------------------------------------------------------------------
__global__ void conv_silu_kernel(const float* __restrict__ xz,
                                 const float* __restrict__ cw,
                                 const float* __restrict__ cb,
                                 float* __restrict__ u)
{
    int gid = blockIdx.x * blockDim.x + threadIdx.x;
    if (gid >= R_TOT * DI) return;
    int d   = gid & (DI - 1);
    int row = gid >> 11;
    int t   = row & 1023;

    float acc = cb[d];
    #pragma unroll
    for (int j = 0; j < 4; j++) {
        int tt = t - 3 + j;
        if (tt >= 0)
            acc = fmaf(xz[(size_t)(row - 3 + j) * (2 * DI) + d], cw[d * 4 + j], acc);
    }
    u[gid] = acc / (1.f + __expf(-acc));
}

// ---------------------------------------------------------------------------
// x_proj split-K (fp32) + reduce (writes fp32 + bf16)
// ---------------------------------------------------------------------------
__global__ void __launch_bounds__(256, 2)
xproj_splitk(const float* __restrict__ u,
             const float* __restrict__ w,
             float* __restrict__ partial)
{
    __shared__ float As[16][132];
    __shared__ float Bs[16][100];

    const int tid = threadIdx.x;
    const int m0  = blockIdx.x * 128;
    const int kc  = blockIdx.y * (DI / XSPLIT);
    const int kk  = tid & 15;
    const int rp  = tid >> 4;
    const int ty  = tid >> 4;
    const int tx  = tid & 15;

    float acc[8][6];
    #pragma unroll
    for (int i = 0; i < 8; i++)
        #pragma unroll
        for (int j = 0; j < 6; j++) acc[i][j] = 0.f;

    for (int kt = 0; kt < DI / XSPLIT; kt += 16) {
        const int kb = kc + kt;
        #pragma unroll
        for (int p = 0; p < 8; p++)
            As[kk][rp + p * 16] = u[(size_t)(m0 + rp + p * 16) * DI + kb + kk];
        #pragma unroll
        for (int q = 0; q < 6; q++)
            Bs[kk][rp + q * 16] = w[(size_t)(rp + q * 16) * DI + kb + kk];
        __syncthreads();

        #pragma unroll
        for (int k = 0; k < 16; k++) {
            float av[8], bv[6];
            #pragma unroll
            for (int i = 0; i < 8; i++) av[i] = As[k][ty + i * 16];
            #pragma unroll
            for (int j = 0; j < 6; j++) bv[j] = Bs[k][tx + j * 16];
            #pragma unroll
            for (int i = 0; i < 8; i++)
                #pragma unroll
                for (int j = 0; j < 6; j++)
                    acc[i][j] = fmaf(av[i], bv[j], acc[i][j]);
        }
        __syncthreads();
    }

    float* outp = partial + (size_t)blockIdx.y * R_TOT * 96;
    #pragma unroll
    for (int i = 0; i < 8; i++)
        #pragma unroll
        for (int j = 0; j < 6; j++)
            outp[(size_t)(m0 + ty + i * 16) * 96 + tx + j * 16] = acc[i][j];
}

__global__ void xproj_reduce(const float* __restrict__ partial,
                             float* __restrict__ proj,
                             __nv_bfloat16* __restrict__ projb)
{
    int idx = blockIdx.x * blockDim.x + threadIdx.x;
    if (idx >= R_TOT * 96) return;
    float s = 0.f;
    #pragma unroll
    for (int p = 0; p < XSPLIT; p++)
        s += partial[(size_t)p * R_TOT * 96 + idx];
    proj[idx]  = s;
    projb[idx] = __float2bfloat16(s);
}

// ---------------------------------------------------------------------------
// Selective scan, smem-staged chunks; writes y as bf16.
// ---------------------------------------------------------------------------
__global__ void __launch_bounds__(256)
scan_kernel(const float* __restrict__ dt,
            const float* __restrict__ u,
            const float* __restrict__ proj,
            const float* __restrict__ xz,
            const float* __restrict__ A_log,
            const float* __restrict__ D_diag,
            __nv_bfloat16* __restrict__ yb)
{
    __shared__ float s_dt[TCH][16];
    __shared__ float s_u [TCH][16];
    __shared__ float s_z [TCH][16];
    __shared__ float s_bc[TCH][32];
    __shared__ float s_y [TCH][16];

    const int tid  = threadIdx.x;
    const int n    = tid & 15;
    const int g    = tid >> 4;
    const int dblk = blockIdx.x & 127;
    const int b    = blockIdx.x >> 7;
    const int d0   = dblk * 16;
    const int d    = d0 + g;
    const int bbase = b * 1024;

    const float Adn = -__expf(A_log[d * DST + n]);
    const float Dd  = D_diag[d];

    const int lr  = tid >> 2;
    const int lc4 = (tid & 3) * 4;

    float state = 0.f;
    for (int c = 0; c < 1024 / TCH; c++) {
        const int t0 = c * TCH;
        const size_t grow = (size_t)(bbase + t0 + lr);

        *(float4*)&s_dt[lr][lc4] = *(const float4*)(dt + grow * DI + d0 + lc4);
        *(float4*)&s_u [lr][lc4] = *(const float4*)(u  + grow * DI + d0 + lc4);
        *(float4*)&s_z [lr][lc4] = *(const float4*)(xz + grow * (2 * DI) + DI + d0 + lc4);
        #pragma unroll
        for (int p = 0; p < 2; p++) {
            int idx = tid + p * 256;
            int r2  = idx >> 3;
            int c8  = (idx & 7) * 4;
            *(float4*)&s_bc[r2][c8] =
                *(const float4*)(proj + (size_t)(bbase + t0 + r2) * 96 + 64 + c8);
        }
        __syncthreads();

        #pragma unroll 4
        for (int t = 0; t < TCH; t++) {
            float dtv = s_dt[t][g];
            float uv  = s_u [t][g];
            float Bv  = s_bc[t][n];
            float Cv  = s_bc[t][16 + n];

            float dA = __expf(dtv * Adn);
            state = fmaf(dA, state, (dtv * uv) * Bv);

            float part = state * Cv;
            part += __shfl_xor_sync(0xffffffffu, part, 1);
            part += __shfl_xor_sync(0xffffffffu, part, 2);
            part += __shfl_xor_sync(0xffffffffu, part, 4);
            part += __shfl_xor_sync(0xffffffffu, part, 8);

            if (n == 0) {
                float zv = s_z[t][g];
                float sz = zv / (1.f + __expf(-zv));
                s_y[t][g] = (part + Dd * uv) * sz;
            }
        }
        __syncthreads();

        float4 v = *(const float4*)&s_y[lr][lc4];
        uint2 o = make_uint2(pack_bf2(v.x, v.y), pack_bf2(v.z, v.w));
        *(uint2*)(yb + grow * DI + d0 + lc4) = o;
        __syncthreads();
    }
}

// ---------------------------------------------------------------------------
extern "C" void kernel_launch(void* const* d_in, const int* in_sizes, int n_in,
                              void* d_out, int out_size)
{
    const float* x          = (const float*)d_in[0];
    const float* norm_w     = (const float*)d_in[1];
    const float* in_proj_w  = (const float*)d_in[2];
    const float* conv_w     = (const float*)d_in[3];
    const float* conv_b     = (const float*)d_in[4];
    const float* x_proj_w   = (const float*)d_in[5];
    const float* dt_proj_w  = (const float*)d_in[6];
    const float* dt_proj_b  = (const float*)d_in[7];
    const float* A_log      = (const float*)d_in[8];
    const float* D_diag     = (const float*)d_in[9];
    const float* out_proj_w = (const float*)d_in[10];
    float* out = (float*)d_out;

    float *xz, *u, *projp, *proj, *dtb;
    __nv_bfloat16 *xnb, *pjb, *yb, *w1b, *w2b, *w3b;
    cudaGetSymbolAddress((void**)&xz,    g_xz);
    cudaGetSymbolAddress((void**)&u,     g_u);
    cudaGetSymbolAddress((void**)&projp, g_projp);
    cudaGetSymbolAddress((void**)&proj,  g_proj);
    cudaGetSymbolAddress((void**)&dtb,   g_dt);
    cudaGetSymbolAddress((void**)&xnb,   g_xnb);
    cudaGetSymbolAddress((void**)&pjb,   g_pjb);
    cudaGetSymbolAddress((void**)&yb,    g_yb);
    cudaGetSymbolAddress((void**)&w1b,   g_w1b);
    cudaGetSymbolAddress((void**)&w2b,   g_w2b);
    cudaGetSymbolAddress((void**)&w3b,   g_w3b);

    cudaFuncSetAttribute(gemm_cp, cudaFuncAttributeMaxDynamicSharedMemorySize,
                         SMEM_DYN);

    // 0) weight conversions (bf16)
    cvt_bf16_kernel<<<(2 * DI * DM / 4 + 255) / 256, 256>>>(in_proj_w, w1b,
                                                            2 * DI * DM / 4);
    cvt_bf16_kernel<<<(DI * DTR / 4 + 255) / 256, 256>>>(dt_proj_w, w2b,
                                                         DI * DTR / 4);
    cvt_bf16_kernel<<<(DM * DI / 4 + 255) / 256, 256>>>(out_proj_w, w3b,
                                                        DM * DI / 4);

    // 1) RMSNorm -> bf16
    rmsnorm_kernel<<<R_TOT, 256>>>(x, norm_w, xnb);

    // 2) in_proj: 2048 x 4096 x 1024
    gemm_cp<<<dim3(32, 16), 256, SMEM_DYN>>>(xnb, DM, w1b, DM, xz, 2 * DI,
                                             DM, 0, nullptr, nullptr);

    // 3) conv + silu
    conv_silu_kernel<<<(R_TOT * DI) / 256, 256>>>(xz, conv_w, conv_b, u);

    // 4) x_proj split-K + reduce
    xproj_splitk<<<dim3(16, XSPLIT), 256>>>(u, x_proj_w, projp);
    xproj_reduce<<<(R_TOT * 96 + 255) / 256, 256>>>(projp, proj, pjb);

    // 5) dt: softplus(proj[:, :64] @ dt_proj_w^T + b): 2048 x 2048 x 64
    gemm_cp<<<dim3(16, 16), 256, SMEM_DYN>>>(pjb, 96, w2b, DTR, dtb, DI,
                                             DTR, 1, dt_proj_b, nullptr);

    // 6) selective scan -> y (bf16)
    scan_kernel<<<256, 256>>>(dtb, u, proj, xz, A_log, D_diag, yb);

    // 7) out_proj + residual: 2048 x 1024 x 2048
    gemm_cp<<<dim3(8, 16), 256, SMEM_DYN>>>(yb, DI, w3b, DI, out, DM,
                                            DI, 2, nullptr, x);
}

// round 7
// speedup vs baseline: 4.7160x; 1.0859x over previous
#include <cuda_runtime.h>
#include <cuda_bf16.h>
#include <cstdint>

// ---------------------------------------------------------------------------
// Mamba block. GEMMs: bf16 mma.sync + cp.async, 128B-row XOR-swizzled smem
// (conflict-free stores AND ldmatrix). BATCH=2 SEQ=1024 DM=1024 DI=2048
// ---------------------------------------------------------------------------

#define R_TOT   2048
#define DM      1024
#define DI      2048
#define DTR     64
#define DST     16
#define XS2     8           // x_proj split-K factor
#define PSTR    128         // padded proj row stride
#define TCH     64          // scan time-chunk

// fp32 scratch
__device__ float g_xz    [R_TOT * 2 * DI];
__device__ float g_u     [R_TOT * DI];
__device__ float g_projp [XS2 * R_TOT * PSTR];
__device__ float g_proj  [R_TOT * PSTR];
__device__ float g_dt    [R_TOT * DI];
// bf16 scratch
__device__ __nv_bfloat16 g_xnb [R_TOT * DM];
__device__ __nv_bfloat16 g_ub  [R_TOT * DI];
__device__ __nv_bfloat16 g_pjb [R_TOT * PSTR];
__device__ __nv_bfloat16 g_yb  [R_TOT * DI];
__device__ __nv_bfloat16 g_w1b [2 * DI * DM];    // in_proj_w
__device__ __nv_bfloat16 g_w2b [DI * DTR];       // dt_proj_w
__device__ __nv_bfloat16 g_w3b [DM * DI];        // out_proj_w
__device__ __nv_bfloat16 g_wxb [128 * DI];       // x_proj_w zero-padded to 128 rows

// ---------------------------------------------------------------------------
__device__ __forceinline__ uint32_t smem_u32(const void* p) {
    uint32_t a;
    asm("{ .reg .u64 t; cvta.to.shared.u64 t, %1; cvt.u32.u64 %0, t; }"
        : "=r"(a) : "l"(p));
    return a;
}
__device__ __forceinline__ uint32_t pack_bf2(float x, float y) {
    __nv_bfloat162 h = __floats2bfloat162_rn(x, y);
    return *(uint32_t*)&h;
}

#define LDSM_X4(r0, r1, r2, r3, addr)                                          \
    asm volatile("ldmatrix.sync.aligned.m8n8.x4.shared.b16 {%0,%1,%2,%3}, [%4];" \
                 : "=r"(r0), "=r"(r1), "=r"(r2), "=r"(r3) : "r"(addr))

#define MMA_BF16(d, a0, a1, a2, a3, b0, b1)                                    \
    asm volatile("mma.sync.aligned.m16n8k16.row.col.f32.bf16.bf16.f32 "        \
                 "{%0,%1,%2,%3}, {%4,%5,%6,%7}, {%8,%9}, {%0,%1,%2,%3};"       \
                 : "+f"(d[0]), "+f"(d[1]), "+f"(d[2]), "+f"(d[3])              \
                 : "r"(a0), "r"(a1), "r"(a2), "r"(a3), "r"(b0), "r"(b1))

#define CP16(saddr, gptr)                                                      \
    asm volatile("cp.async.cg.shared.global [%0], [%1], 16;"                   \
                 :: "r"(saddr), "l"(gptr))
#define CP_COMMIT() asm volatile("cp.async.commit_group;" ::: "memory")
#define CP_WAIT0()  asm volatile("cp.async.wait_group 0;" ::: "memory")
#define CP_WAIT1()  asm volatile("cp.async.wait_group 1;" ::: "memory")

// ---------------------------------------------------------------------------
// bf16 GEMM:  C[m,n] = sum_k A[m,k]*B[n,k]
// 128x128 tile, BK=64 halves (128B rows), XOR-swizzled smem, 3-stage cp.async.
// grid (nTiles, mTiles, kSplits): kOff = z*kLen, C += z*zStride.
// Requirements: M,N mult 128 (buffers padded); kLen mult 64; lda/ldb mult 8.
// epi: 0 plain, 1 softplus(acc+bias[n]), 2 acc+resid
// ---------------------------------------------------------------------------
#define STG2      32768                 // per stage: A 16K + B 16K
#define SMEM_DYN2 (3 * STG2)            // 98304 B

__global__ void __launch_bounds__(256, 2)
gemm_cp2(const __nv_bfloat16* __restrict__ A, int lda,
         const __nv_bfloat16* __restrict__ B, int ldb,
         float* __restrict__ C, int ldc, size_t zStride,
         int kLen, int epi,
         const float* __restrict__ bias,
         const float* __restrict__ resid)
{
    extern __shared__ char smem[];
    const uint32_t sbase = smem_u32(smem);
    const int tid  = threadIdx.x;
    const int lane = tid & 31;
    const int wid  = tid >> 5;
    const int wm   = wid >> 2;
    const int wn   = wid & 3;
    const int m0   = blockIdx.y * 128;
    const int n0   = blockIdx.x * 128;
    const int kOff = blockIdx.z * kLen;
    C += (size_t)blockIdx.z * zStride;

    // staging: row = tid>>1 (0..127), 4 chunks of 16B each for A and B
    const int row  = tid >> 1;
    const int cgrp = (tid & 1) * 4;
    const int rk   = row & 7;
    const __nv_bfloat16* aP = A + (size_t)(m0 + row) * lda + kOff;
    const __nv_bfloat16* bP = B + (size_t)(n0 + row) * ldb + kOff;
    const uint32_t rowB = (uint32_t)row * 128u;

    // ldmatrix row-byte offsets (within a stage)
    uint32_t aRowOff[4], bRowOff[2];
    #pragma unroll
    for (int mi = 0; mi < 4; mi++)
        aRowOff[mi] = (uint32_t)((wm * 64 + mi * 16 + (lane & 15)) * 128);
    #pragma unroll
    for (int nj = 0; nj < 2; nj++)
        bRowOff[nj] = (uint32_t)((wn * 32 + nj * 16 + (lane & 7) +
                                  ((lane & 16) >> 1)) * 128) + 16384u;
    const uint32_t lk = (uint32_t)(lane & 7);

    float acc[4][4][4];
    #pragma unroll
    for (int i = 0; i < 4; i++)
        #pragma unroll
        for (int j = 0; j < 4; j++)
            #pragma unroll
            for (int q = 0; q < 4; q++) acc[i][j][q] = 0.f;

    const int iters = kLen >> 6;

    // prologue: up to 2 stages
    #pragma unroll
    for (int p = 0; p < 2; p++) {
        if (p < iters) {
            const uint32_t so = sbase + (uint32_t)p * STG2;
            #pragma unroll
            for (int j = 0; j < 4; j++) {
                const int ch = cgrp + j;
                const uint32_t sw = (uint32_t)(ch ^ rk) << 4;
                CP16(so + rowB + sw,          aP + p * 64 + ch * 8);
                CP16(so + 16384 + rowB + sw,  bP + p * 64 + ch * 8);
            }
            CP_COMMIT();
        }
    }

    int slot = 0, nslot = (iters >= 3) ? 2 : 0;
    for (int it = 0; it < iters; it++) {
        if (it == iters - 1) { CP_WAIT0(); } else { CP_WAIT1(); }
        __syncthreads();

        if (it + 2 < iters) {
            const int st = it + 2;
            const uint32_t so = sbase + (uint32_t)nslot * STG2;
            #pragma unroll
            for (int j = 0; j < 4; j++) {
                const int ch = cgrp + j;
                const uint32_t sw = (uint32_t)(ch ^ rk) << 4;
                CP16(so + rowB + sw,         aP + st * 64 + ch * 8);
                CP16(so + 16384 + rowB + sw, bP + st * 64 + ch * 8);
            }
            CP_COMMIT();
            nslot = (nslot == 2) ? 0 : nslot + 1;
        }

        const uint32_t sS = sbase + (uint32_t)slot * STG2;
        #pragma unroll
        for (int ks = 0; ks < 4; ks++) {
            const uint32_t swA = (uint32_t)((ks * 2 + (lane >> 4)) ^ lk) << 4;
            const uint32_t swB = (uint32_t)((ks * 2 + ((lane >> 3) & 1)) ^ lk) << 4;
            uint32_t a[4][4];
            #pragma unroll
            for (int mi = 0; mi < 4; mi++)
                LDSM_X4(a[mi][0], a[mi][1], a[mi][2], a[mi][3],
                        sS + aRowOff[mi] + swA);
            uint32_t b[4][2];
            #pragma unroll
            for (int nj = 0; nj < 2; nj++) {
                uint32_t r0, r1, r2, r3;
                LDSM_X4(r0, r1, r2, r3, sS + bRowOff[nj] + swB);
                b[2 * nj][0] = r0; b[2 * nj][1] = r1;
                b[2 * nj + 1][0] = r2; b[2 * nj + 1][1] = r3;
            }
            #pragma unroll
            for (int mi = 0; mi < 4; mi++)
                #pragma unroll
                for (int ni = 0; ni < 4; ni++)
                    MMA_BF16(acc[mi][ni], a[mi][0], a[mi][1], a[mi][2], a[mi][3],
                             b[ni][0], b[ni][1]);
        }
        slot = (slot == 2) ? 0 : slot + 1;
    }

    // epilogue
    const int er = lane >> 2;
    const int ec = (lane & 3) * 2;
    #pragma unroll
    for (int mi = 0; mi < 4; mi++) {
        int gm = m0 + wm * 64 + mi * 16 + er;
        #pragma unroll
        for (int ni = 0; ni < 4; ni++) {
            int gn = n0 + wn * 32 + ni * 8 + ec;
            #pragma unroll
            for (int half = 0; half < 2; half++) {
                int gmm = gm + half * 8;
                float v0 = acc[mi][ni][half * 2];
                float v1 = acc[mi][ni][half * 2 + 1];
                if (epi == 1) {
                    v0 += bias[gn];
                    v1 += bias[gn + 1];
                    v0 = (v0 > 20.f) ? v0 : log1pf(__expf(v0));
                    v1 = (v1 > 20.f) ? v1 : log1pf(__expf(v1));
                } else if (epi == 2) {
                    const float2 r = *(const float2*)(resid + (size_t)gmm * ldc + gn);
                    v0 += r.x;
                    v1 += r.y;
                }
                *(float2*)(C + (size_t)gmm * ldc + gn) = make_float2(v0, v1);
            }
        }
    }
}

// ---------------------------------------------------------------------------
// fp32 -> bf16 (vectorized), n % 4 == 0
// ---------------------------------------------------------------------------
__global__ void cvt_bf16_kernel(const float* __restrict__ in,
                                __nv_bfloat16* __restrict__ out, int n4)
{
    int i = blockIdx.x * blockDim.x + threadIdx.x;
    if (i >= n4) return;
    float4 v = *(const float4*)(in + (size_t)i * 4);
    uint2 o = make_uint2(pack_bf2(v.x, v.y), pack_bf2(v.z, v.w));
    *(uint2*)(out + (size_t)i * 4) = o;
}

// x_proj_w (96 x DI) -> bf16 zero-padded (128 x DI)
__global__ void cvt_pad_x_kernel(const float* __restrict__ in,
                                 __nv_bfloat16* __restrict__ out)
{
    int i = blockIdx.x * blockDim.x + threadIdx.x;       // float4 index
    if (i >= 128 * DI / 4) return;
    int row = (i * 4) / DI;
    uint2 o;
    if (row < 96) {
        float4 v = *(const float4*)(in + (size_t)i * 4);
        o = make_uint2(pack_bf2(v.x, v.y), pack_bf2(v.z, v.w));
    } else {
        o = make_uint2(0u, 0u);
    }
    *(uint2*)(out + (size_t)i * 4) = o;
}

// ---------------------------------------------------------------------------
// RMSNorm -> bf16
// ---------------------------------------------------------------------------
__global__ void rmsnorm_kernel(const float* __restrict__ x,
                               const float* __restrict__ w,
                               __nv_bfloat16* __restrict__ out)
{
    const int row = blockIdx.x;
    const int tid = threadIdx.x;
    const float* xr = x + (size_t)row * DM;

    float4 v = *(const float4*)(xr + tid * 4);
    float s = v.x * v.x + v.y * v.y + v.z * v.z + v.w * v.w;
    #pragma unroll
    for (int o = 16; o; o >>= 1) s += __shfl_xor_sync(0xffffffffu, s, o);

    __shared__ float sm[8];
    if ((tid & 31) == 0) sm[tid >> 5] = s;
    __syncthreads();
    float tot = sm[0] + sm[1] + sm[2] + sm[3] + sm[4] + sm[5] + sm[6] + sm[7];
    float scale = rsqrtf(tot * (1.f / DM) + 1e-6f);

    float4 wv = *(const float4*)(w + tid * 4);
    uint2 o = make_uint2(pack_bf2(v.x * scale * wv.x, v.y * scale * wv.y),
                         pack_bf2(v.z * scale * wv.z, v.w * scale * wv.w));
    *(uint2*)(out + (size_t)row * DM + tid * 4) = o;
}

// ---------------------------------------------------------------------------
// Depthwise causal conv (4 taps) + SiLU -> u fp32 + bf16
// ---------------------------------------------------------------------------
__global__ void conv_silu_kernel(const float* __restrict__ xz,
                                 const float* __restrict__ cw,
                                 const float* __restrict__ cb,
                                 float* __restrict__ u,
                                 __nv_bfloat16* __restrict__ ub)
{
    int gid = blockIdx.x * blockDim.x + threadIdx.x;
    if (gid >= R_TOT * DI) return;
    int d   = gid & (DI - 1);
    int row = gid >> 11;
    int t   = row & 1023;

    float acc = cb[d];
    #pragma unroll
    for (int j = 0; j < 4; j++) {
        int tt = t - 3 + j;
        if (tt >= 0)
            acc = fmaf(xz[(size_t)(row - 3 + j) * (2 * DI) + d], cw[d * 4 + j], acc);
    }
    float s = acc / (1.f + __expf(-acc));
    u[gid]  = s;
    ub[gid] = __float2bfloat16(s);
}

// ---------------------------------------------------------------------------
// x_proj split-K reduce: sum XS2 partials -> proj fp32 + pjb bf16 (stride 128)
// ---------------------------------------------------------------------------
__global__ void xproj_reduce(const float* __restrict__ partial,
                             float* __restrict__ proj,
                             __nv_bfloat16* __restrict__ projb)
{
    int idx = blockIdx.x * blockDim.x + threadIdx.x;
    if (idx >= R_TOT * PSTR) return;
    float s = 0.f;
    #pragma unroll
    for (int p = 0; p < XS2; p++)
        s += partial[(size_t)p * R_TOT * PSTR + idx];
    proj[idx]  = s;
    projb[idx] = __float2bfloat16(s);
}

// ---------------------------------------------------------------------------
// Selective scan, smem-staged chunks; proj stride PSTR; writes y bf16.
// ---------------------------------------------------------------------------
__global__ void __launch_bounds__(256)
scan_kernel(const float* __restrict__ dt,
            const float* __restrict__ u,
            const float* __restrict__ proj,
            const float* __restrict__ xz,
            const float* __restrict__ A_log,
            const float* __restrict__ D_diag,
            __nv_bfloat16* __restrict__ yb)
{
    __shared__ float s_dt[TCH][16];
    __shared__ float s_u [TCH][16];
    __shared__ float s_z [TCH][16];
    __shared__ float s_bc[TCH][32];
    __shared__ float s_y [TCH][16];

    const int tid  = threadIdx.x;
    const int n    = tid & 15;
    const int g    = tid >> 4;
    const int dblk = blockIdx.x & 127;
    const int b    = blockIdx.x >> 7;
    const int d0   = dblk * 16;
    const int d    = d0 + g;
    const int bbase = b * 1024;

    const float Adn = -__expf(A_log[d * DST + n]);
    const float Dd  = D_diag[d];

    const int lr  = tid >> 2;
    const int lc4 = (tid & 3) * 4;

    float state = 0.f;
    for (int c = 0; c < 1024 / TCH; c++) {
        const int t0 = c * TCH;
        const size_t grow = (size_t)(bbase + t0 + lr);

        *(float4*)&s_dt[lr][lc4] = *(const float4*)(dt + grow * DI + d0 + lc4);
        *(float4*)&s_u [lr][lc4] = *(const float4*)(u  + grow * DI + d0 + lc4);
        *(float4*)&s_z [lr][lc4] = *(const float4*)(xz + grow * (2 * DI) + DI + d0 + lc4);
        #pragma unroll
        for (int p = 0; p < 2; p++) {
            int idx = tid + p * 256;
            int r2  = idx >> 3;
            int c8  = (idx & 7) * 4;
            *(float4*)&s_bc[r2][c8] =
                *(const float4*)(proj + (size_t)(bbase + t0 + r2) * PSTR + 64 + c8);
        }
        __syncthreads();

        #pragma unroll 4
        for (int t = 0; t < TCH; t++) {
            float dtv = s_dt[t][g];
            float uv  = s_u [t][g];
            float Bv  = s_bc[t][n];
            float Cv  = s_bc[t][16 + n];

            float dA = __expf(dtv * Adn);
            state = fmaf(dA, state, (dtv * uv) * Bv);

            float part = state * Cv;
            part += __shfl_xor_sync(0xffffffffu, part, 1);
            part += __shfl_xor_sync(0xffffffffu, part, 2);
            part += __shfl_xor_sync(0xffffffffu, part, 4);
            part += __shfl_xor_sync(0xffffffffu, part, 8);

            if (n == 0) {
                float zv = s_z[t][g];
                float sz = zv / (1.f + __expf(-zv));
                s_y[t][g] = (part + Dd * uv) * sz;
            }
        }
        __syncthreads();

        float4 v = *(const float4*)&s_y[lr][lc4];
        uint2 o = make_uint2(pack_bf2(v.x, v.y), pack_bf2(v.z, v.w));
        *(uint2*)(yb + grow * DI + d0 + lc4) = o;
        __syncthreads();
    }
}

// ---------------------------------------------------------------------------
extern "C" void kernel_launch(void* const* d_in, const int* in_sizes, int n_in,
                              void* d_out, int out_size)
{
    const float* x          = (const float*)d_in[0];
    const float* norm_w     = (const float*)d_in[1];
    const float* in_proj_w  = (const float*)d_in[2];
    const float* conv_w     = (const float*)d_in[3];
    const float* conv_b     = (const float*)d_in[4];
    const float* x_proj_w   = (const float*)d_in[5];
    const float* dt_proj_w  = (const float*)d_in[6];
    const float* dt_proj_b  = (const float*)d_in[7];
    const float* A_log      = (const float*)d_in[8];
    const float* D_diag     = (const float*)d_in[9];
    const float* out_proj_w = (const float*)d_in[10];
    float* out = (float*)d_out;

    float *xz, *u, *projp, *proj, *dtb;
    __nv_bfloat16 *xnb, *ub, *pjb, *yb, *w1b, *w2b, *w3b, *wxb;
    cudaGetSymbolAddress((void**)&xz,    g_xz);
    cudaGetSymbolAddress((void**)&u,     g_u);
    cudaGetSymbolAddress((void**)&projp, g_projp);
    cudaGetSymbolAddress((void**)&proj,  g_proj);
    cudaGetSymbolAddress((void**)&dtb,   g_dt);
    cudaGetSymbolAddress((void**)&xnb,   g_xnb);
    cudaGetSymbolAddress((void**)&ub,    g_ub);
    cudaGetSymbolAddress((void**)&pjb,   g_pjb);
    cudaGetSymbolAddress((void**)&yb,    g_yb);
    cudaGetSymbolAddress((void**)&w1b,   g_w1b);
    cudaGetSymbolAddress((void**)&w2b,   g_w2b);
    cudaGetSymbolAddress((void**)&w3b,   g_w3b);
    cudaGetSymbolAddress((void**)&wxb,   g_wxb);

    cudaFuncSetAttribute(gemm_cp2, cudaFuncAttributeMaxDynamicSharedMemorySize,
                         SMEM_DYN2);

    // 0) weight conversions
    cvt_bf16_kernel<<<(2 * DI * DM / 4 + 255) / 256, 256>>>(in_proj_w, w1b,
                                                            2 * DI * DM / 4);
    cvt_bf16_kernel<<<(DI * DTR / 4 + 255) / 256, 256>>>(dt_proj_w, w2b,
                                                         DI * DTR / 4);
    cvt_bf16_kernel<<<(DM * DI / 4 + 255) / 256, 256>>>(out_proj_w, w3b,
                                                        DM * DI / 4);
    cvt_pad_x_kernel<<<(128 * DI / 4 + 255) / 256, 256>>>(x_proj_w, wxb);

    // 1) RMSNorm -> bf16
    rmsnorm_kernel<<<R_TOT, 256>>>(x, norm_w, xnb);

    // 2) in_proj: 2048 x 4096 x 1024
    gemm_cp2<<<dim3(32, 16, 1), 256, SMEM_DYN2>>>(
        xnb, DM, w1b, DM, xz, 2 * DI, 0, DM, 0, nullptr, nullptr);

    // 3) conv + silu -> u fp32 + bf16
    conv_silu_kernel<<<(R_TOT * DI) / 256, 256>>>(xz, conv_w, conv_b, u, ub);

    // 4) x_proj (tensor, split-K=8, padded N=128) + reduce
    gemm_cp2<<<dim3(1, 16, XS2), 256, SMEM_DYN2>>>(
        ub, DI, wxb, DI, projp, PSTR, (size_t)R_TOT * PSTR,
        DI / XS2, 0, nullptr, nullptr);
    xproj_reduce<<<(R_TOT * PSTR + 255) / 256, 256>>>(projp, proj, pjb);

    // 5) dt: softplus(proj[:, :64] @ dt_proj_w^T + b): 2048 x 2048 x 64
    gemm_cp2<<<dim3(16, 16, 1), 256, SMEM_DYN2>>>(
        pjb, PSTR, w2b, DTR, dtb, DI, 0, DTR, 1, dt_proj_b, nullptr);

    // 6) selective scan -> y (bf16)
    scan_kernel<<<256, 256>>>(dtb, u, proj, xz, A_log, D_diag, yb);

    // 7) out_proj + residual: 2048 x 1024 x 2048
    gemm_cp2<<<dim3(8, 16, 1), 256, SMEM_DYN2>>>(
        yb, DI, w3b, DI, out, DM, 0, DI, 2, nullptr, x);
}

// round 9
// speedup vs baseline: 4.7843x; 1.0145x over previous
#include <cuda_runtime.h>
#include <cuda_bf16.h>
#include <cstdint>

// ---------------------------------------------------------------------------
// Mamba block. bf16 mma.sync GEMMs (cp.async, XOR-swizzled 128B rows).
// All inter-stage tensors bf16 except dt (fp32). BATCH=2 SEQ=1024
// ---------------------------------------------------------------------------

#define R_TOT   2048
#define DM      1024
#define DI      2048
#define DTR     64
#define DST     16
#define XS2     8
#define PSTR    128
#define TCH     64

// fp32 scratch
__device__ float g_projp [XS2 * R_TOT * PSTR];
__device__ float g_dt    [R_TOT * DI];
// bf16 scratch
__device__ __nv_bfloat16 g_xzb [R_TOT * 2 * DI];
__device__ __nv_bfloat16 g_xnb [R_TOT * DM];
__device__ __nv_bfloat16 g_ub  [R_TOT * DI];
__device__ __nv_bfloat16 g_pjb [R_TOT * PSTR];
__device__ __nv_bfloat16 g_yb  [R_TOT * DI];
__device__ __nv_bfloat16 g_w1b [2 * DI * DM];
__device__ __nv_bfloat16 g_w2b [DI * DTR];
__device__ __nv_bfloat16 g_w3b [DM * DI];
__device__ __nv_bfloat16 g_wxb [128 * DI];

// ---------------------------------------------------------------------------
__device__ __forceinline__ uint32_t smem_u32(const void* p) {
    uint32_t a;
    asm("{ .reg .u64 t; cvta.to.shared.u64 t, %1; cvt.u32.u64 %0, t; }"
        : "=r"(a) : "l"(p));
    return a;
}
__device__ __forceinline__ uint32_t pack_bf2(float x, float y) {
    __nv_bfloat162 h = __floats2bfloat162_rn(x, y);
    return *(uint32_t*)&h;
}

#define LDSM_X4(r0, r1, r2, r3, addr)                                          \
    asm volatile("ldmatrix.sync.aligned.m8n8.x4.shared.b16 {%0,%1,%2,%3}, [%4];" \
                 : "=r"(r0), "=r"(r1), "=r"(r2), "=r"(r3) : "r"(addr))

#define MMA_BF16(d, a0, a1, a2, a3, b0, b1)                                    \
    asm volatile("mma.sync.aligned.m16n8k16.row.col.f32.bf16.bf16.f32 "        \
                 "{%0,%1,%2,%3}, {%4,%5,%6,%7}, {%8,%9}, {%0,%1,%2,%3};"       \
                 : "+f"(d[0]), "+f"(d[1]), "+f"(d[2]), "+f"(d[3])              \
                 : "r"(a0), "r"(a1), "r"(a2), "r"(a3), "r"(b0), "r"(b1))

#define CP16(saddr, gptr)                                                      \
    asm volatile("cp.async.cg.shared.global [%0], [%1], 16;"                   \
                 :: "r"(saddr), "l"(gptr))
#define CP_COMMIT() asm volatile("cp.async.commit_group;" ::: "memory")
#define CP_WAIT0()  asm volatile("cp.async.wait_group 0;" ::: "memory")
#define CP_WAIT1()  asm volatile("cp.async.wait_group 1;" ::: "memory")

// ---------------------------------------------------------------------------
// bf16 GEMM: C[m,n] = sum_k A[m,k]*B[n,k]; 128x128 tile, BK=64, 3-stage.
// grid (nTiles, mTiles, kSplits). epi: 0 fp32, 1 softplus fp32(+bias),
// 2 fp32+resid, 4 bf16 store.
// ---------------------------------------------------------------------------
#define STG2      32768
#define SMEM_DYN2 (3 * STG2)

__global__ void __launch_bounds__(256, 2)
gemm_cp2(const __nv_bfloat16* __restrict__ A, int lda,
         const __nv_bfloat16* __restrict__ B, int ldb,
         float* __restrict__ C, int ldc, size_t zStride,
         int kLen, int epi,
         const float* __restrict__ bias,
         const float* __restrict__ resid)
{
    extern __shared__ char smem[];
    const uint32_t sbase = smem_u32(smem);
    const int tid  = threadIdx.x;
    const int lane = tid & 31;
    const int wid  = tid >> 5;
    const int wm   = wid >> 2;
    const int wn   = wid & 3;
    const int m0   = blockIdx.y * 128;
    const int n0   = blockIdx.x * 128;
    const int kOff = blockIdx.z * kLen;
    C += (size_t)blockIdx.z * zStride;

    const int row  = tid >> 1;
    const int cgrp = (tid & 1) * 4;
    const int rk   = row & 7;
    const __nv_bfloat16* aP = A + (size_t)(m0 + row) * lda + kOff;
    const __nv_bfloat16* bP = B + (size_t)(n0 + row) * ldb + kOff;
    const uint32_t rowB = (uint32_t)row * 128u;

    uint32_t aRowOff[4], bRowOff[2];
    #pragma unroll
    for (int mi = 0; mi < 4; mi++)
        aRowOff[mi] = (uint32_t)((wm * 64 + mi * 16 + (lane & 15)) * 128);
    #pragma unroll
    for (int nj = 0; nj < 2; nj++)
        bRowOff[nj] = (uint32_t)((wn * 32 + nj * 16 + (lane & 7) +
                                  ((lane & 16) >> 1)) * 128) + 16384u;
    const uint32_t lk = (uint32_t)(lane & 7);

    float acc[4][4][4];
    #pragma unroll
    for (int i = 0; i < 4; i++)
        #pragma unroll
        for (int j = 0; j < 4; j++)
            #pragma unroll
            for (int q = 0; q < 4; q++) acc[i][j][q] = 0.f;

    const int iters = kLen >> 6;

    #pragma unroll
    for (int p = 0; p < 2; p++) {
        if (p < iters) {
            const uint32_t so = sbase + (uint32_t)p * STG2;
            #pragma unroll
            for (int j = 0; j < 4; j++) {
                const int ch = cgrp + j;
                const uint32_t sw = (uint32_t)(ch ^ rk) << 4;
                CP16(so + rowB + sw,          aP + p * 64 + ch * 8);
                CP16(so + 16384 + rowB + sw,  bP + p * 64 + ch * 8);
            }
            CP_COMMIT();
        }
    }

    int slot = 0, nslot = (iters >= 3) ? 2 : 0;
    for (int it = 0; it < iters; it++) {
        if (it == iters - 1) { CP_WAIT0(); } else { CP_WAIT1(); }
        __syncthreads();

        if (it + 2 < iters) {
            const int st = it + 2;
            const uint32_t so = sbase + (uint32_t)nslot * STG2;
            #pragma unroll
            for (int j = 0; j < 4; j++) {
                const int ch = cgrp + j;
                const uint32_t sw = (uint32_t)(ch ^ rk) << 4;
                CP16(so + rowB + sw,         aP + st * 64 + ch * 8);
                CP16(so + 16384 + rowB + sw, bP + st * 64 + ch * 8);
            }
            CP_COMMIT();
            nslot = (nslot == 2) ? 0 : nslot + 1;
        }

        const uint32_t sS = sbase + (uint32_t)slot * STG2;
        #pragma unroll
        for (int ks = 0; ks < 4; ks++) {
            const uint32_t swA = (uint32_t)((ks * 2 + (lane >> 4)) ^ lk) << 4;
            const uint32_t swB = (uint32_t)((ks * 2 + ((lane >> 3) & 1)) ^ lk) << 4;
            uint32_t a[4][4];
            #pragma unroll
            for (int mi = 0; mi < 4; mi++)
                LDSM_X4(a[mi][0], a[mi][1], a[mi][2], a[mi][3],
                        sS + aRowOff[mi] + swA);
            uint32_t b[4][2];
            #pragma unroll
            for (int nj = 0; nj < 2; nj++) {
                uint32_t r0, r1, r2, r3;
                LDSM_X4(r0, r1, r2, r3, sS + bRowOff[nj] + swB);
                b[2 * nj][0] = r0; b[2 * nj][1] = r1;
                b[2 * nj + 1][0] = r2; b[2 * nj + 1][1] = r3;
            }
            #pragma unroll
            for (int mi = 0; mi < 4; mi++)
                #pragma unroll
                for (int ni = 0; ni < 4; ni++)
                    MMA_BF16(acc[mi][ni], a[mi][0], a[mi][1], a[mi][2], a[mi][3],
                             b[ni][0], b[ni][1]);
        }
        slot = (slot == 2) ? 0 : slot + 1;
    }

    // epilogue
    const int er = lane >> 2;
    const int ec = (lane & 3) * 2;
    __nv_bfloat16* Cb = (__nv_bfloat16*)C;
    #pragma unroll
    for (int mi = 0; mi < 4; mi++) {
        int gm = m0 + wm * 64 + mi * 16 + er;
        #pragma unroll
        for (int ni = 0; ni < 4; ni++) {
            int gn = n0 + wn * 32 + ni * 8 + ec;
            #pragma unroll
            for (int half = 0; half < 2; half++) {
                int gmm = gm + half * 8;
                float v0 = acc[mi][ni][half * 2];
                float v1 = acc[mi][ni][half * 2 + 1];
                if (epi == 4) {
                    *(uint32_t*)(Cb + (size_t)gmm * ldc + gn) = pack_bf2(v0, v1);
                } else if (epi == 1) {
                    v0 += bias[gn];
                    v1 += bias[gn + 1];
                    v0 = (v0 > 20.f) ? v0 : log1pf(__expf(v0));
                    v1 = (v1 > 20.f) ? v1 : log1pf(__expf(v1));
                    *(float2*)(C + (size_t)gmm * ldc + gn) = make_float2(v0, v1);
                } else if (epi == 2) {
                    const float2 r = *(const float2*)(resid + (size_t)gmm * ldc + gn);
                    *(float2*)(C + (size_t)gmm * ldc + gn) =
                        make_float2(v0 + r.x, v1 + r.y);
                } else {
                    *(float2*)(C + (size_t)gmm * ldc + gn) = make_float2(v0, v1);
                }
            }
        }
    }
}

// ---------------------------------------------------------------------------
__global__ void cvt_bf16_kernel(const float* __restrict__ in,
                                __nv_bfloat16* __restrict__ out, int n4)
{
    int i = blockIdx.x * blockDim.x + threadIdx.x;
    if (i >= n4) return;
    float4 v = *(const float4*)(in + (size_t)i * 4);
    *(uint2*)(out + (size_t)i * 4) =
        make_uint2(pack_bf2(v.x, v.y), pack_bf2(v.z, v.w));
}

__global__ void cvt_pad_x_kernel(const float* __restrict__ in,
                                 __nv_bfloat16* __restrict__ out)
{
    int i = blockIdx.x * blockDim.x + threadIdx.x;
    if (i >= 128 * DI / 4) return;
    int row = (i * 4) / DI;
    uint2 o;
    if (row < 96) {
        float4 v = *(const float4*)(in + (size_t)i * 4);
        o = make_uint2(pack_bf2(v.x, v.y), pack_bf2(v.z, v.w));
    } else {
        o = make_uint2(0u, 0u);
    }
    *(uint2*)(out + (size_t)i * 4) = o;
}

// ---------------------------------------------------------------------------
__global__ void rmsnorm_kernel(const float* __restrict__ x,
                               const float* __restrict__ w,
                               __nv_bfloat16* __restrict__ out)
{
    const int row = blockIdx.x;
    const int tid = threadIdx.x;
    const float* xr = x + (size_t)row * DM;

    float4 v = *(const float4*)(xr + tid * 4);
    float s = v.x * v.x + v.y * v.y + v.z * v.z + v.w * v.w;
    #pragma unroll
    for (int o = 16; o; o >>= 1) s += __shfl_xor_sync(0xffffffffu, s, o);

    __shared__ float sm[8];
    if ((tid & 31) == 0) sm[tid >> 5] = s;
    __syncthreads();
    float tot = sm[0] + sm[1] + sm[2] + sm[3] + sm[4] + sm[5] + sm[6] + sm[7];
    float scale = rsqrtf(tot * (1.f / DM) + 1e-6f);

    float4 wv = *(const float4*)(w + tid * 4);
    *(uint2*)(out + (size_t)row * DM + tid * 4) =
        make_uint2(pack_bf2(v.x * scale * wv.x, v.y * scale * wv.y),
                   pack_bf2(v.z * scale * wv.z, v.w * scale * wv.w));
}

// ---------------------------------------------------------------------------
// Depthwise causal conv + SiLU: reads xzb bf16, writes ub bf16
// ---------------------------------------------------------------------------
__global__ void conv_silu_kernel(const __nv_bfloat16* __restrict__ xzb,
                                 const float* __restrict__ cw,
                                 const float* __restrict__ cb,
                                 __nv_bfloat16* __restrict__ ub)
{
    int gid = blockIdx.x * blockDim.x + threadIdx.x;
    if (gid >= R_TOT * DI) return;
    int d   = gid & (DI - 1);
    int row = gid >> 11;
    int t   = row & 1023;

    float acc = cb[d];
    #pragma unroll
    for (int j = 0; j < 4; j++) {
        int tt = t - 3 + j;
        if (tt >= 0)
            acc = fmaf(__bfloat162float(xzb[(size_t)(row - 3 + j) * (2 * DI) + d]),
                       cw[d * 4 + j], acc);
    }
    float s = acc / (1.f + __expf(-acc));
    ub[gid] = __float2bfloat16(s);
}

// ---------------------------------------------------------------------------
__global__ void xproj_reduce(const float* __restrict__ partial,
                             __nv_bfloat16* __restrict__ projb)
{
    int idx = blockIdx.x * blockDim.x + threadIdx.x;
    if (idx >= R_TOT * PSTR) return;
    float s = 0.f;
    #pragma unroll
    for (int p = 0; p < XS2; p++)
        s += partial[(size_t)p * R_TOT * PSTR + idx];
    projb[idx] = __float2bfloat16(s);
}

// ---------------------------------------------------------------------------
// Selective scan: dt fp32; u/z/B/C bf16; packed float2 smem; y out bf16.
// ---------------------------------------------------------------------------
__global__ void __launch_bounds__(256)
scan_kernel(const float* __restrict__ dt,
            const __nv_bfloat16* __restrict__ ub,
            const __nv_bfloat16* __restrict__ pjb,
            const __nv_bfloat16* __restrict__ xzb,
            const float* __restrict__ A_log,
            const float* __restrict__ D_diag,
            __nv_bfloat16* __restrict__ yb)
{
    __shared__ float2 s_du[TCH][16];
    __shared__ float2 s_bc[TCH][16];
    __shared__ float  s_z [TCH][16];
    __shared__ float  s_y [TCH][16];

    const int tid  = threadIdx.x;
    const int n    = tid & 15;
    const int g    = tid >> 4;
    const int dblk = blockIdx.x & 127;
    const int b    = blockIdx.x >> 7;
    const int d0   = dblk * 16;
    const int d    = d0 + g;
    const int bbase = b * 1024;

    const float Adn = -__expf(A_log[d * DST + n]);
    const float Dd  = D_diag[d];

    const int lr  = tid >> 2;          // 0..63 row
    const int lc4 = (tid & 3) * 4;     // 4 channels / 4 states

    float state = 0.f;
    for (int c = 0; c < 1024 / TCH; c++) {
        const int t0 = c * TCH;
        const size_t grow = (size_t)(bbase + t0 + lr);

        // dt (fp32) + u (bf16) -> packed
        float4 dv = *(const float4*)(dt + grow * DI + d0 + lc4);
        uint2 uu = *(const uint2*)(ub + grow * DI + d0 + lc4);
        __nv_bfloat162 u01 = *(__nv_bfloat162*)&uu.x;
        __nv_bfloat162 u23 = *(__nv_bfloat162*)&uu.y;
        s_du[lr][lc4 + 0] = make_float2(dv.x, __bfloat162float(u01.x));
        s_du[lr][lc4 + 1] = make_float2(dv.y, __bfloat162float(u01.y));
        s_du[lr][lc4 + 2] = make_float2(dv.z, __bfloat162float(u23.x));
        s_du[lr][lc4 + 3] = make_float2(dv.w, __bfloat162float(u23.y));

        // z (bf16)
        uint2 zz = *(const uint2*)(xzb + grow * (2 * DI) + DI + d0 + lc4);
        __nv_bfloat162 z01 = *(__nv_bfloat162*)&zz.x;
        __nv_bfloat162 z23 = *(__nv_bfloat162*)&zz.y;
        s_z[lr][lc4 + 0] = __bfloat162float(z01.x);
        s_z[lr][lc4 + 1] = __bfloat162float(z01.y);
        s_z[lr][lc4 + 2] = __bfloat162float(z23.x);
        s_z[lr][lc4 + 3] = __bfloat162float(z23.y);

        // B,C (bf16) -> packed {B_n, C_n}
        {
            uint2 bb = *(const uint2*)(pjb + grow * PSTR + 64 + lc4);
            uint2 cc = *(const uint2*)(pjb + grow * PSTR + 80 + lc4);
            __nv_bfloat162 b01 = *(__nv_bfloat162*)&bb.x;
            __nv_bfloat162 b23 = *(__nv_bfloat162*)&bb.y;
            __nv_bfloat162 c01 = *(__nv_bfloat162*)&cc.x;
            __nv_bfloat162 c23 = *(__nv_bfloat162*)&cc.y;
            s_bc[lr][lc4 + 0] = make_float2(__bfloat162float(b01.x), __bfloat162float(c01.x));
            s_bc[lr][lc4 + 1] = make_float2(__bfloat162float(b01.y), __bfloat162float(c01.y));
            s_bc[lr][lc4 + 2] = make_float2(__bfloat162float(b23.x), __bfloat162float(c23.x));
            s_bc[lr][lc4 + 3] = make_float2(__bfloat162float(b23.y), __bfloat162float(c23.y));
        }
        __syncthreads();

        #pragma unroll 8
        for (int t = 0; t < TCH; t++) {
            float2 du = s_du[t][g];
            float2 bc = s_bc[t][n];

            float dA = __expf(du.x * Adn);
            state = fmaf(dA, state, (du.x * du.y) * bc.x);

            float part = state * bc.y;
            part += __shfl_xor_sync(0xffffffffu, part, 1);
            part += __shfl_xor_sync(0xffffffffu, part, 2);
            part += __shfl_xor_sync(0xffffffffu, part, 4);
            part += __shfl_xor_sync(0xffffffffu, part, 8);

            if (n == 0) {
                float zv = s_z[t][g];
                float sz = zv / (1.f + __expf(-zv));
                s_y[t][g] = (part + Dd * du.y) * sz;
            }
        }
        __syncthreads();

        float4 v = *(const float4*)&s_y[lr][lc4];
        *(uint2*)(yb + grow * DI + d0 + lc4) =
            make_uint2(pack_bf2(v.x, v.y), pack_bf2(v.z, v.w));
        __syncthreads();
    }
}

// ---------------------------------------------------------------------------
extern "C" void kernel_launch(void* const* d_in, const int* in_sizes, int n_in,
                              void* d_out, int out_size)
{
    const float* x          = (const float*)d_in[0];
    const float* norm_w     = (const float*)d_in[1];
    const float* in_proj_w  = (const float*)d_in[2];
    const float* conv_w     = (const float*)d_in[3];
    const float* conv_b     = (const float*)d_in[4];
    const float* x_proj_w   = (const float*)d_in[5];
    const float* dt_proj_w  = (const float*)d_in[6];
    const float* dt_proj_b  = (const float*)d_in[7];
    const float* A_log      = (const float*)d_in[8];
    const float* D_diag     = (const float*)d_in[9];
    const float* out_proj_w = (const float*)d_in[10];
    float* out = (float*)d_out;

    float *projp, *dtb;
    __nv_bfloat16 *xzb, *xnb, *ub, *pjb, *yb, *w1b, *w2b, *w3b, *wxb;
    cudaGetSymbolAddress((void**)&projp, g_projp);
    cudaGetSymbolAddress((void**)&dtb,   g_dt);
    cudaGetSymbolAddress((void**)&xzb,   g_xzb);
    cudaGetSymbolAddress((void**)&xnb,   g_xnb);
    cudaGetSymbolAddress((void**)&ub,    g_ub);
    cudaGetSymbolAddress((void**)&pjb,   g_pjb);
    cudaGetSymbolAddress((void**)&yb,    g_yb);
    cudaGetSymbolAddress((void**)&w1b,   g_w1b);
    cudaGetSymbolAddress((void**)&w2b,   g_w2b);
    cudaGetSymbolAddress((void**)&w3b,   g_w3b);
    cudaGetSymbolAddress((void**)&wxb,   g_wxb);

    cudaFuncSetAttribute(gemm_cp2, cudaFuncAttributeMaxDynamicSharedMemorySize,
                         SMEM_DYN2);

    // Launch order arranged so in_proj GEMM is the 4th launch (ncu capture).
    // 1) in_proj weights
    cvt_bf16_kernel<<<(2 * DI * DM / 4 + 255) / 256, 256>>>(in_proj_w, w1b,
                                                            2 * DI * DM / 4);
    // 2) RMSNorm -> bf16
    rmsnorm_kernel<<<R_TOT, 256>>>(x, norm_w, xnb);
    // 3) out_proj weights
    cvt_bf16_kernel<<<(DM * DI / 4 + 255) / 256, 256>>>(out_proj_w, w3b,
                                                        DM * DI / 4);
    // 4) in_proj: 2048 x 4096 x 1024 -> xzb (bf16)
    gemm_cp2<<<dim3(32, 16, 1), 256, SMEM_DYN2>>>(
        xnb, DM, w1b, DM, (float*)xzb, 2 * DI, 0, DM, 4, nullptr, nullptr);
    // 5) conv + silu -> ub
    conv_silu_kernel<<<(R_TOT * DI) / 256, 256>>>(xzb, conv_w, conv_b, ub);
    // 6) x_proj weights (padded)
    cvt_pad_x_kernel<<<(128 * DI / 4 + 255) / 256, 256>>>(x_proj_w, wxb);
    // 7) x_proj split-K=8 -> fp32 partials
    gemm_cp2<<<dim3(1, 16, XS2), 256, SMEM_DYN2>>>(
        ub, DI, wxb, DI, projp, PSTR, (size_t)R_TOT * PSTR,
        DI / XS2, 0, nullptr, nullptr);
    // 8) reduce -> pjb (bf16)
    xproj_reduce<<<(R_TOT * PSTR + 255) / 256, 256>>>(projp, pjb);
    // 9) dt weights
    cvt_bf16_kernel<<<(DI * DTR / 4 + 255) / 256, 256>>>(dt_proj_w, w2b,
                                                         DI * DTR / 4);
    // 10) dt: softplus(...) -> fp32
    gemm_cp2<<<dim3(16, 16, 1), 256, SMEM_DYN2>>>(
        pjb, PSTR, w2b, DTR, dtb, DI, 0, DTR, 1, dt_proj_b, nullptr);
    // 11) selective scan -> yb (bf16)
    scan_kernel<<<256, 256>>>(dtb, ub, pjb, xzb, A_log, D_diag, yb);
    // 12) out_proj + residual -> out (fp32)
    gemm_cp2<<<dim3(8, 16, 1), 256, SMEM_DYN2>>>(
        yb, DI, w3b, DI, out, DM, 0, DI, 2, nullptr, x);
}